// round 6
// baseline (speedup 1.0000x reference)
#include <cuda_runtime.h>
#include <math.h>
#include <stdint.h>

#define BB 2
#define SS 2048
#define DD 1024
#define HH 16
#define DHD 64
#define NROWS (BB*SS)          /* 4096 */
#define ROPE_LOG2C 0.4152410118609203f   /* log2(10000)/32 */

/* Scratch (allocation-free rule) */
__device__ float g_x[(size_t)NROWS*DD];
__device__ float g_wq[DD*DD];     /* transposed, tf32-rounded */
__device__ float g_wk[DD*DD];
__device__ float g_wv[DD*DD];
__device__ float g_wo[DD*DD];
__device__ float g_q[BB*HH*SS*DHD];        /* [b,h,s,d] */
__device__ float g_k[BB*HH*SS*DHD];        /* [b,h,s,d] */
__device__ float g_v[BB*HH*SS*DHD];        /* [b,h,d,s]  TRANSPOSED */
__device__ float g_ctx[(size_t)NROWS*DD];

__device__ __forceinline__ uint32_t tf32_of(float x) {
    uint32_t u;
    asm("cvt.rna.tf32.f32 %0, %1;" : "=r"(u) : "f"(x));
    return u;
}
__device__ __forceinline__ float tf32f(float x) {
    return __uint_as_float(tf32_of(x));
}
__device__ __forceinline__ uint32_t smem_u32_of(const void* p) {
    uint32_t a;
    asm("{ .reg .u64 t; cvta.to.shared.u64 t, %1; cvt.u32.u64 %0, t; }" : "=r"(a) : "l"(p));
    return a;
}

#define MMA_TF32(c, a, b0, b1) \
    asm volatile("mma.sync.aligned.m16n8k8.row.col.f32.tf32.tf32.f32 " \
        "{%0,%1,%2,%3}, {%4,%5,%6,%7}, {%8,%9}, {%0,%1,%2,%3};" \
        : "+f"((c)[0]), "+f"((c)[1]), "+f"((c)[2]), "+f"((c)[3]) \
        : "r"((a)[0]), "r"((a)[1]), "r"((a)[2]), "r"((a)[3]), \
          "r"(b0), "r"(b1))

#define LDSM4(r, addr) \
    asm volatile("ldmatrix.sync.aligned.m8n8.x4.shared.b16 {%0,%1,%2,%3}, [%4];" \
        : "=r"((r)[0]), "=r"((r)[1]), "=r"((r)[2]), "=r"((r)[3]) : "r"(addr))

#define CP16(dst, src) \
    asm volatile("cp.async.cg.shared.global [%0], [%1], 16;" :: "r"(dst), "l"(src))
#define CPCOMMIT() asm volatile("cp.async.commit_group;" ::: "memory")
#define CPWAIT(n)  asm volatile("cp.async.wait_group %0;" :: "n"(n) : "memory")

/* ================================================================== */
/* Pre-pass 1: round X to tf32. grid 4096 x 256 (4 floats/thread).    */
/* ================================================================== */
__global__ void round_x_kernel(const float* __restrict__ X)
{
    const size_t idx = (size_t)(blockIdx.x * 256 + threadIdx.x) * 4;
    float4 v = *reinterpret_cast<const float4*>(X + idx);
    v.x = tf32f(v.x); v.y = tf32f(v.y); v.z = tf32f(v.z); v.w = tf32f(v.w);
    *reinterpret_cast<float4*>(g_x + idx) = v;
}

/* ================================================================== */
/* Pre-pass 2: transpose + round the 4 weight matrices.               */
/* grid (32, 32, 4), block (32, 8), 32x32 smem tiles.                 */
/* ================================================================== */
__global__ void wtrans_kernel(const float* __restrict__ Wq,
                              const float* __restrict__ Wk,
                              const float* __restrict__ Wv,
                              const float* __restrict__ Wo)
{
    __shared__ float t[32][33];
    const int z = blockIdx.z;
    const float* src = (z == 0) ? Wq : ((z == 1) ? Wk : ((z == 2) ? Wv : Wo));
    float* dst = (z == 0) ? g_wq : ((z == 1) ? g_wk : ((z == 2) ? g_wv : g_wo));
    const int r0 = blockIdx.y * 32, c0 = blockIdx.x * 32;
    const int tx = threadIdx.x, ty = threadIdx.y;
#pragma unroll
    for (int k = 0; k < 4; k++)
        t[ty + 8 * k][tx] = tf32f(src[(size_t)(r0 + ty + 8 * k) * DD + c0 + tx]);
    __syncthreads();
#pragma unroll
    for (int k = 0; k < 4; k++)
        dst[(size_t)(c0 + ty + 8 * k) * DD + r0 + tx] = t[tx][ty + 8 * k];
}

/* ================================================================== */
/* GEMM: CTA 128x128, 4 warps (64x64), BK=16, cp.async x4, ldmatrix.  */
/* A smem [m][16] pitch 20; B smem [n][k16] pitch 20 (W transposed).  */
/* ================================================================== */
#define GM_PITCHB 80                        /* 20 floats */
#define GM_ABYTES (128*GM_PITCHB)           /* 10240 */
#define GM_STAGE  (2*GM_ABYTES)             /* 20480 */
#define GM_NSTAGE 4
#define GM_SMEM   (GM_NSTAGE * GM_STAGE)    /* 81920 */

__device__ __forceinline__ void gemm_issue_stage(
    const float* __restrict__ A, const float* __restrict__ Wt,
    int row0, int col0, int s, uint32_t sm)
{
    const int tid = threadIdx.x;
    const uint32_t base = sm + (uint32_t)(s & 3) * GM_STAGE;
    const int r = tid >> 2, q = tid & 3;
#pragma unroll
    for (int it = 0; it < 4; it++) {
        const int rr = r + it * 32;
        CP16(base + (uint32_t)(rr * GM_PITCHB + q * 16),
             A + (size_t)(row0 + rr) * DD + s * 16 + q * 4);
        CP16(base + GM_ABYTES + (uint32_t)(rr * GM_PITCHB + q * 16),
             Wt + (size_t)(col0 + rr) * DD + s * 16 + q * 4);
    }
}

__device__ __forceinline__ void gemm_tc3(
    const float* __restrict__ A, const float* __restrict__ Wt,
    int row0, int col0, uint32_t sm, float acc[4][8][4])
{
    const int lane = threadIdx.x & 31, warp = threadIdx.x >> 5;
    const int wm = warp >> 1, wn = warp & 1;
    const uint32_t lrow = (uint32_t)(lane & 15);
    const uint32_t lcol = (uint32_t)(lane >> 4) * 16;

    uint32_t a_off[4], b_off[4];
#pragma unroll
    for (int i = 0; i < 4; i++)
        a_off[i] = (uint32_t)(wm * 64 + i * 16 + lrow) * GM_PITCHB + lcol;
#pragma unroll
    for (int jp = 0; jp < 4; jp++)
        b_off[jp] = GM_ABYTES + (uint32_t)(wn * 64 + jp * 16 + lrow) * GM_PITCHB + lcol;

    gemm_issue_stage(A, Wt, row0, col0, 0, sm); CPCOMMIT();
    gemm_issue_stage(A, Wt, row0, col0, 1, sm); CPCOMMIT();
    gemm_issue_stage(A, Wt, row0, col0, 2, sm); CPCOMMIT();

    for (int kt = 0; kt < 64; kt++) {
        CPWAIT(2);
        __syncthreads();
        if (kt + 3 < 64) gemm_issue_stage(A, Wt, row0, col0, kt + 3, sm);
        CPCOMMIT();

        const uint32_t stage = sm + (uint32_t)(kt & 3) * GM_STAGE;
#pragma unroll
        for (int k8 = 0; k8 < 2; k8++) {
            uint32_t a[4][4], bt[4][4];
#pragma unroll
            for (int i = 0; i < 4; i++)
                LDSM4(a[i], stage + a_off[i] + k8 * 32);
#pragma unroll
            for (int jp = 0; jp < 4; jp++)
                LDSM4(bt[jp], stage + b_off[jp] + k8 * 32);
#pragma unroll
            for (int i = 0; i < 4; i++)
#pragma unroll
                for (int j = 0; j < 8; j++) {
                    const int jp = j >> 1, sel = j & 1;
                    MMA_TF32(acc[i][j], a[i], bt[jp][sel], bt[jp][sel + 2]);
                }
        }
    }
}

/* ------------------------------------------------------------------ */
__global__ void __launch_bounds__(128, 2)
qkv_tc3_kernel()
{
    extern __shared__ __align__(16) float smem[];
    const uint32_t sm = smem_u32_of(smem);
    const int which = blockIdx.z;
    const float* __restrict__ Wt = (which == 0) ? g_wq : ((which == 1) ? g_wk : g_wv);
    const int row0 = blockIdx.y * 128, col0 = blockIdx.x * 128;

    float acc[4][8][4];
#pragma unroll
    for (int i = 0; i < 4; i++)
#pragma unroll
        for (int j = 0; j < 8; j++)
#pragma unroll
            for (int c = 0; c < 4; c++) acc[i][j][c] = 0.f;

    gemm_tc3(g_x, Wt, row0, col0, sm, acc);

    const int lane = threadIdx.x & 31, warp = threadIdx.x >> 5;
    const int wm = warp >> 1, wn = warp & 1;
    const int ar = lane >> 2, ac = lane & 3;
    const int h = (col0 >> 6) + wn;     /* warp n-tile 64 == one head */

    if (which < 2) {
        float* __restrict__ dst = (which == 0) ? g_q : g_k;
        float freqs[8];
#pragma unroll
        for (int j = 0; j < 8; j++)
            freqs[j] = exp2f(-(float)(j * 4 + ac) * ROPE_LOG2C);
#pragma unroll
        for (int i = 0; i < 4; i++) {
#pragma unroll
            for (int half = 0; half < 2; half++) {
                const int row = row0 + wm * 64 + i * 16 + ar + half * 8;
                const int b_ = row >> 11, s = row & (SS - 1);
                float* drow = dst + ((size_t)(b_ * HH + h) * SS + s) * DHD;
                const float sf = (float)s;
#pragma unroll
                for (int j = 0; j < 8; j++) {
                    const int dh = j * 8 + 2 * ac;
                    const float e = acc[i][j][half * 2], o = acc[i][j][half * 2 + 1];
                    float sn, cs;
                    sincosf(sf * freqs[j], &sn, &cs);
                    *reinterpret_cast<float2*>(&drow[dh]) =
                        make_float2(tf32f(e * cs - o * sn), tf32f(e * sn + o * cs));
                }
            }
        }
    } else {
        /* V: store TRANSPOSED [b,h,d,s] */
#pragma unroll
        for (int i = 0; i < 4; i++) {
#pragma unroll
            for (int half = 0; half < 2; half++) {
                const int row = row0 + wm * 64 + i * 16 + ar + half * 8;
                const int b_ = row >> 11, s = row & (SS - 1);
                float* dbase = g_v + ((size_t)(b_ * HH + h)) * DHD * SS;
#pragma unroll
                for (int j = 0; j < 8; j++) {
                    const int dh = j * 8 + 2 * ac;
                    dbase[(size_t)dh * SS + s]       = tf32f(acc[i][j][half * 2]);
                    dbase[(size_t)(dh + 1) * SS + s] = tf32f(acc[i][j][half * 2 + 1]);
                }
            }
        }
    }
}

/* ------------------------------------------------------------------ */
__global__ void __launch_bounds__(128, 2)
out_tc3_kernel(const float* __restrict__ bo, float* __restrict__ out)
{
    extern __shared__ __align__(16) float smem[];
    const uint32_t sm = smem_u32_of(smem);
    const int row0 = blockIdx.y * 128, col0 = blockIdx.x * 128;

    float acc[4][8][4];
#pragma unroll
    for (int i = 0; i < 4; i++)
#pragma unroll
        for (int j = 0; j < 8; j++)
#pragma unroll
            for (int c = 0; c < 4; c++) acc[i][j][c] = 0.f;

    gemm_tc3(g_ctx, g_wo, row0, col0, sm, acc);

    const int lane = threadIdx.x & 31, warp = threadIdx.x >> 5;
    const int wm = warp >> 1, wn = warp & 1;
    const int ar = lane >> 2, ac = lane & 3;

#pragma unroll
    for (int i = 0; i < 4; i++) {
        const int r = row0 + wm * 64 + i * 16 + ar;
#pragma unroll
        for (int j = 0; j < 8; j++) {
            const int col = col0 + wn * 64 + j * 8 + 2 * ac;
            const float bx = bo[col], by = bo[col + 1];
            *reinterpret_cast<float2*>(&out[(size_t)r * DD + col]) =
                make_float2(acc[i][j][0] + bx, acc[i][j][1] + by);
            *reinterpret_cast<float2*>(&out[(size_t)(r + 8) * DD + col]) =
                make_float2(acc[i][j][2] + bx, acc[i][j][3] + by);
        }
    }
}

/* ================================================================== */
/* Flash attention v3: q-tile 128, k-tile 64, 4 warps x 32 q-rows.    */
/* ldmatrix for Q/K/P/V fragments. V in [b,h,d,s] layout.             */
/* ================================================================== */
#define AT_PITCHB 272                       /* 68 floats */
#define AT_QP_BYTES (128*AT_PITCHB)         /* 34816 */
#define AT_KV_BYTES (64*AT_PITCHB)          /* 17408 */
#define AT_KOFF     AT_QP_BYTES
#define AT_VOFF     (AT_QP_BYTES + 2*AT_KV_BYTES)
#define AT_SMEM     (AT_QP_BYTES + 4*AT_KV_BYTES)   /* 104448 */

__global__ void __launch_bounds__(128, 2)
attn_tc3_kernel()
{
    extern __shared__ __align__(16) float smem[];
    const uint32_t sm = smem_u32_of(smem);
    const int bh = blockIdx.y;
    const int qt = gridDim.x - 1 - blockIdx.x;   /* heavy-first */
    const float* __restrict__ Q  = g_q + (size_t)bh * SS * DHD;
    const float* __restrict__ K  = g_k + (size_t)bh * SS * DHD;
    const float* __restrict__ Vt = g_v + (size_t)bh * DHD * SS;  /* [d][s] */

    const int tid = threadIdx.x;
    const int lane = tid & 31, warp = tid >> 5;
    const int ar = lane >> 2, ac = lane & 3;
    const int nk = 2 * qt + 2;

    const uint32_t lrow = (uint32_t)(lane & 15);
    const uint32_t lcol = (uint32_t)(lane >> 4) * 16;

    auto issue_kv = [&](int kt, int buf) {
#pragma unroll
        for (int it = 0; it < 8; it++) {
            const int idx = tid + it * 128;
            const int r = idx >> 4, q = idx & 15;
            CP16(sm + (uint32_t)(AT_KOFF + buf * AT_KV_BYTES + r * AT_PITCHB + q * 16),
                 K + (size_t)(kt * 64 + r) * DHD + q * 4);
            CP16(sm + (uint32_t)(AT_VOFF + buf * AT_KV_BYTES + r * AT_PITCHB + q * 16),
                 Vt + (size_t)r * SS + kt * 64 + q * 4);
        }
    };

#pragma unroll
    for (int it = 0; it < 16; it++) {
        const int idx = tid + it * 128;
        const int r = idx >> 4, q = idx & 15;
        CP16(sm + (uint32_t)(r * AT_PITCHB + q * 16),
             Q + (size_t)(qt * 128 + r) * DHD + q * 4);
    }
    issue_kv(0, 0);
    CPCOMMIT();
    issue_kv(1, 1);
    CPCOMMIT();

    CPWAIT(1);
    __syncthreads();

    /* Q fragments -> registers via ldmatrix */
    uint32_t qf[2][8][4];
#pragma unroll
    for (int i = 0; i < 2; i++) {
        const uint32_t qoff = (uint32_t)(warp * 32 + i * 16 + lrow) * AT_PITCHB + lcol;
#pragma unroll
        for (int k8 = 0; k8 < 8; k8++)
            LDSM4(qf[i][k8], sm + qoff + k8 * 32);
    }
    __syncthreads();   /* all Q frags read before P overwrites region */

    float m[2][2], l[2][2], o[2][8][4];
#pragma unroll
    for (int i = 0; i < 2; i++) {
        m[i][0] = m[i][1] = -1e30f;
        l[i][0] = l[i][1] = 0.f;
#pragma unroll
        for (int j = 0; j < 8; j++)
#pragma unroll
            for (int c = 0; c < 4; c++) o[i][j][c] = 0.f;
    }

    float* Ps = smem;   /* reuse Q region for P (warp-private rows) */

    for (int kt = 0; kt < nk; kt++) {
        CPWAIT(1);
        __syncthreads();
        const int buf = kt & 1;
        const uint32_t kbase = sm + AT_KOFF + buf * AT_KV_BYTES;
        const uint32_t vbase = sm + AT_VOFF + buf * AT_KV_BYTES;

        /* ---- S = Q K^T ---- */
        float s[2][8][4];
#pragma unroll
        for (int i = 0; i < 2; i++)
#pragma unroll
            for (int j = 0; j < 8; j++)
#pragma unroll
                for (int c = 0; c < 4; c++) s[i][j][c] = 0.f;

#pragma unroll
        for (int k8 = 0; k8 < 8; k8++) {
            uint32_t kb[4][4];
#pragma unroll
            for (int jp = 0; jp < 4; jp++)
                LDSM4(kb[jp], kbase + (uint32_t)(jp * 16 + lrow) * AT_PITCHB + lcol + k8 * 32);
#pragma unroll
            for (int j = 0; j < 8; j++) {
                const int jp = j >> 1, sel = j & 1;
                MMA_TF32(s[0][j], qf[0][k8], kb[jp][sel], kb[jp][sel + 2]);
                MMA_TF32(s[1][j], qf[1][k8], kb[jp][sel], kb[jp][sel + 2]);
            }
        }

        /* ---- scale + causal mask ---- */
        const bool domask = (kt >= 2 * qt);
        const int dshift = (kt - 2 * qt) * 64;
#pragma unroll
        for (int i = 0; i < 2; i++) {
            const int r0 = warp * 32 + i * 16 + ar, r1 = r0 + 8;
#pragma unroll
            for (int j = 0; j < 8; j++) {
                float v0 = s[i][j][0] * 0.125f, v1 = s[i][j][1] * 0.125f;
                float v2 = s[i][j][2] * 0.125f, v3 = s[i][j][3] * 0.125f;
                if (domask) {
                    const int c = j * 8 + 2 * ac + dshift;
                    if (c     > r0) v0 = -1e30f;
                    if (c + 1 > r0) v1 = -1e30f;
                    if (c     > r1) v2 = -1e30f;
                    if (c + 1 > r1) v3 = -1e30f;
                }
                s[i][j][0] = v0; s[i][j][1] = v1; s[i][j][2] = v2; s[i][j][3] = v3;
            }
        }

        /* ---- online softmax ---- */
#pragma unroll
        for (int i = 0; i < 2; i++) {
            float mx0 = -1e30f, mx1 = -1e30f;
#pragma unroll
            for (int j = 0; j < 8; j++) {
                mx0 = fmaxf(mx0, fmaxf(s[i][j][0], s[i][j][1]));
                mx1 = fmaxf(mx1, fmaxf(s[i][j][2], s[i][j][3]));
            }
            mx0 = fmaxf(mx0, __shfl_xor_sync(0xffffffffu, mx0, 1));
            mx0 = fmaxf(mx0, __shfl_xor_sync(0xffffffffu, mx0, 2));
            mx1 = fmaxf(mx1, __shfl_xor_sync(0xffffffffu, mx1, 1));
            mx1 = fmaxf(mx1, __shfl_xor_sync(0xffffffffu, mx1, 2));

            const float mn0 = fmaxf(m[i][0], mx0), mn1 = fmaxf(m[i][1], mx1);
            const float corr0 = __expf(m[i][0] - mn0), corr1 = __expf(m[i][1] - mn1);
            m[i][0] = mn0; m[i][1] = mn1;

            const int r0 = warp * 32 + i * 16 + ar;
            float ps0 = 0.f, ps1 = 0.f;
#pragma unroll
            for (int j = 0; j < 8; j++) {
                const float p0 = __expf(s[i][j][0] - mn0);
                const float p1 = __expf(s[i][j][1] - mn0);
                const float p2 = __expf(s[i][j][2] - mn1);
                const float p3 = __expf(s[i][j][3] - mn1);
                ps0 += p0 + p1; ps1 += p2 + p3;
                const int c = j * 8 + 2 * ac;
                *reinterpret_cast<float2*>(&Ps[r0 * 68 + c]) =
                    make_float2(tf32f(p0), tf32f(p1));
                *reinterpret_cast<float2*>(&Ps[(r0 + 8) * 68 + c]) =
                    make_float2(tf32f(p2), tf32f(p3));
            }
            ps0 += __shfl_xor_sync(0xffffffffu, ps0, 1);
            ps0 += __shfl_xor_sync(0xffffffffu, ps0, 2);
            ps1 += __shfl_xor_sync(0xffffffffu, ps1, 1);
            ps1 += __shfl_xor_sync(0xffffffffu, ps1, 2);
            l[i][0] = l[i][0] * corr0 + ps0;
            l[i][1] = l[i][1] * corr1 + ps1;
#pragma unroll
            for (int j = 0; j < 8; j++) {
                o[i][j][0] *= corr0; o[i][j][1] *= corr0;
                o[i][j][2] *= corr1; o[i][j][3] *= corr1;
            }
        }
        __syncwarp();

        /* ---- O += P V  (P A-frags + V B-frags via ldmatrix) ---- */
#pragma unroll
        for (int k8 = 0; k8 < 8; k8++) {
            uint32_t pa[2][4], vb[4][4];
#pragma unroll
            for (int i = 0; i < 2; i++)
                LDSM4(pa[i], sm + (uint32_t)(warp * 32 + i * 16 + lrow) * AT_PITCHB
                              + lcol + k8 * 32);
#pragma unroll
            for (int jp = 0; jp < 4; jp++)
                LDSM4(vb[jp], vbase + (uint32_t)(jp * 16 + lrow) * AT_PITCHB
                               + lcol + k8 * 32);
#pragma unroll
            for (int j = 0; j < 8; j++) {
                const int jp = j >> 1, sel = j & 1;
                MMA_TF32(o[0][j], pa[0], vb[jp][sel], vb[jp][sel + 2]);
                MMA_TF32(o[1][j], pa[1], vb[jp][sel], vb[jp][sel + 2]);
            }
        }

        __syncthreads();
        if (kt + 2 < nk) issue_kv(kt + 2, buf);
        CPCOMMIT();
    }

    /* epilogue: normalize, write ctx [B*S, D] (tf32-rounded) */
    const int b_ = bh >> 4, h = bh & (HH - 1);
#pragma unroll
    for (int i = 0; i < 2; i++) {
        const float inv0 = 1.0f / l[i][0], inv1 = 1.0f / l[i][1];
        const int r0 = qt * 128 + warp * 32 + i * 16 + ar;
        float* p0 = g_ctx + (size_t)(b_ * SS + r0) * DD + h * DHD;
        float* p1 = g_ctx + (size_t)(b_ * SS + r0 + 8) * DD + h * DHD;
#pragma unroll
        for (int j = 0; j < 8; j++) {
            const int c = j * 8 + 2 * ac;
            *reinterpret_cast<float2*>(&p0[c]) =
                make_float2(tf32f(o[i][j][0] * inv0), tf32f(o[i][j][1] * inv0));
            *reinterpret_cast<float2*>(&p1[c]) =
                make_float2(tf32f(o[i][j][2] * inv1), tf32f(o[i][j][3] * inv1));
        }
    }
}

/* ------------------------------------------------------------------ */
extern "C" void kernel_launch(void* const* d_in, const int* in_sizes, int n_in,
                              void* d_out, int out_size)
{
    (void)in_sizes; (void)n_in; (void)out_size;
    const float* x  = (const float*)d_in[0];
    const float* Wq = (const float*)d_in[1];
    const float* Wk = (const float*)d_in[2];
    const float* Wv = (const float*)d_in[3];
    const float* Wo = (const float*)d_in[4];
    const float* bo = (const float*)d_in[5];
    float* out = (float*)d_out;

    cudaFuncSetAttribute(qkv_tc3_kernel,  cudaFuncAttributeMaxDynamicSharedMemorySize, GM_SMEM);
    cudaFuncSetAttribute(out_tc3_kernel,  cudaFuncAttributeMaxDynamicSharedMemorySize, GM_SMEM);
    cudaFuncSetAttribute(attn_tc3_kernel, cudaFuncAttributeMaxDynamicSharedMemorySize, AT_SMEM);

    round_x_kernel<<<4096, 256>>>(x);
    wtrans_kernel<<<dim3(32, 32, 4), dim3(32, 8)>>>(Wq, Wk, Wv, Wo);

    dim3 gq(DD / 128, NROWS / 128, 3);
    qkv_tc3_kernel<<<gq, 128, GM_SMEM>>>();

    dim3 ga(SS / 128, BB * HH);
    attn_tc3_kernel<<<ga, 128, AT_SMEM>>>();

    dim3 go(DD / 128, NROWS / 128);
    out_tc3_kernel<<<go, 128, GM_SMEM>>>(bo, out);
}

// round 7
// speedup vs baseline: 1.0125x; 1.0125x over previous
#include <cuda_runtime.h>
#include <math.h>
#include <stdint.h>

#define BB 2
#define SS 2048
#define DD 1024
#define HH 16
#define DHD 64
#define NROWS (BB*SS)          /* 4096 */
#define ROPE_LOG2C 0.4152410118609203f   /* log2(10000)/32 */
#define SM_SCALE_LOG2E 0.1803368801111204f  /* 0.125 * log2(e) */

/* Scratch (allocation-free rule) */
__device__ float g_x[(size_t)NROWS*DD];
__device__ float g_wq[DD*DD];     /* transposed, tf32-rounded */
__device__ float g_wk[DD*DD];
__device__ float g_wv[DD*DD];
__device__ float g_wo[DD*DD];
__device__ float g_q[BB*HH*SS*DHD];        /* [b,h,s,d] */
__device__ float g_k[BB*HH*SS*DHD];        /* [b,h,s,d] */
__device__ float g_v[BB*HH*SS*DHD];        /* [b,h,s,d] */
__device__ float g_ctx[(size_t)NROWS*DD];

__device__ __forceinline__ uint32_t tf32_of(float x) {
    uint32_t u;
    asm("cvt.rna.tf32.f32 %0, %1;" : "=r"(u) : "f"(x));
    return u;
}
__device__ __forceinline__ float tf32f(float x) {
    return __uint_as_float(tf32_of(x));
}
__device__ __forceinline__ uint32_t smem_u32_of(const void* p) {
    uint32_t a;
    asm("{ .reg .u64 t; cvta.to.shared.u64 t, %1; cvt.u32.u64 %0, t; }" : "=r"(a) : "l"(p));
    return a;
}

#define MMA_TF32(c, a, b0, b1) \
    asm volatile("mma.sync.aligned.m16n8k8.row.col.f32.tf32.tf32.f32 " \
        "{%0,%1,%2,%3}, {%4,%5,%6,%7}, {%8,%9}, {%0,%1,%2,%3};" \
        : "+f"((c)[0]), "+f"((c)[1]), "+f"((c)[2]), "+f"((c)[3]) \
        : "r"((a)[0]), "r"((a)[1]), "r"((a)[2]), "r"((a)[3]), \
          "r"(b0), "r"(b1))

#define LDSM4(r, addr) \
    asm volatile("ldmatrix.sync.aligned.m8n8.x4.shared.b16 {%0,%1,%2,%3}, [%4];" \
        : "=r"((r)[0]), "=r"((r)[1]), "=r"((r)[2]), "=r"((r)[3]) : "r"(addr))

#define CP16(dst, src) \
    asm volatile("cp.async.cg.shared.global [%0], [%1], 16;" :: "r"(dst), "l"(src))
#define CPCOMMIT() asm volatile("cp.async.commit_group;" ::: "memory")
#define CPWAIT(n)  asm volatile("cp.async.wait_group %0;" :: "n"(n) : "memory")

/* ================================================================== */
/* Pre-pass 1: round X to tf32.                                       */
/* ================================================================== */
__global__ void round_x_kernel(const float* __restrict__ X)
{
    const size_t idx = (size_t)(blockIdx.x * 256 + threadIdx.x) * 4;
    float4 v = *reinterpret_cast<const float4*>(X + idx);
    v.x = tf32f(v.x); v.y = tf32f(v.y); v.z = tf32f(v.z); v.w = tf32f(v.w);
    *reinterpret_cast<float4*>(g_x + idx) = v;
}

/* ================================================================== */
/* Pre-pass 2: transpose + round the 4 weight matrices.               */
/* ================================================================== */
__global__ void wtrans_kernel(const float* __restrict__ Wq,
                              const float* __restrict__ Wk,
                              const float* __restrict__ Wv,
                              const float* __restrict__ Wo)
{
    __shared__ float t[32][33];
    const int z = blockIdx.z;
    const float* src = (z == 0) ? Wq : ((z == 1) ? Wk : ((z == 2) ? Wv : Wo));
    float* dst = (z == 0) ? g_wq : ((z == 1) ? g_wk : ((z == 2) ? g_wv : g_wo));
    const int r0 = blockIdx.y * 32, c0 = blockIdx.x * 32;
    const int tx = threadIdx.x, ty = threadIdx.y;
#pragma unroll
    for (int k = 0; k < 4; k++)
        t[ty + 8 * k][tx] = tf32f(src[(size_t)(r0 + ty + 8 * k) * DD + c0 + tx]);
    __syncthreads();
#pragma unroll
    for (int k = 0; k < 4; k++)
        dst[(size_t)(c0 + ty + 8 * k) * DD + r0 + tx] = t[tx][ty + 8 * k];
}

/* ================================================================== */
/* GEMM: CTA 128x128, 4 warps (64x64), BK=16, cp.async x4, ldmatrix.  */
/* ================================================================== */
#define GM_PITCHB 80                        /* 20 floats */
#define GM_ABYTES (128*GM_PITCHB)           /* 10240 */
#define GM_STAGE  (2*GM_ABYTES)             /* 20480 */
#define GM_NSTAGE 4
#define GM_SMEM   (GM_NSTAGE * GM_STAGE)    /* 81920 */

__device__ __forceinline__ void gemm_issue_stage(
    const float* __restrict__ A, const float* __restrict__ Wt,
    int row0, int col0, int s, uint32_t sm)
{
    const int tid = threadIdx.x;
    const uint32_t base = sm + (uint32_t)(s & 3) * GM_STAGE;
    const int r = tid >> 2, q = tid & 3;
#pragma unroll
    for (int it = 0; it < 4; it++) {
        const int rr = r + it * 32;
        CP16(base + (uint32_t)(rr * GM_PITCHB + q * 16),
             A + (size_t)(row0 + rr) * DD + s * 16 + q * 4);
        CP16(base + GM_ABYTES + (uint32_t)(rr * GM_PITCHB + q * 16),
             Wt + (size_t)(col0 + rr) * DD + s * 16 + q * 4);
    }
}

__device__ __forceinline__ void gemm_tc3(
    const float* __restrict__ A, const float* __restrict__ Wt,
    int row0, int col0, uint32_t sm, float acc[4][8][4])
{
    const int lane = threadIdx.x & 31, warp = threadIdx.x >> 5;
    const int wm = warp >> 1, wn = warp & 1;
    const uint32_t lrow = (uint32_t)(lane & 15);
    const uint32_t lcol = (uint32_t)(lane >> 4) * 16;

    uint32_t a_off[4], b_off[4];
#pragma unroll
    for (int i = 0; i < 4; i++)
        a_off[i] = (uint32_t)(wm * 64 + i * 16 + lrow) * GM_PITCHB + lcol;
#pragma unroll
    for (int jp = 0; jp < 4; jp++)
        b_off[jp] = GM_ABYTES + (uint32_t)(wn * 64 + jp * 16 + lrow) * GM_PITCHB + lcol;

    gemm_issue_stage(A, Wt, row0, col0, 0, sm); CPCOMMIT();
    gemm_issue_stage(A, Wt, row0, col0, 1, sm); CPCOMMIT();
    gemm_issue_stage(A, Wt, row0, col0, 2, sm); CPCOMMIT();

    for (int kt = 0; kt < 64; kt++) {
        CPWAIT(2);
        __syncthreads();
        if (kt + 3 < 64) gemm_issue_stage(A, Wt, row0, col0, kt + 3, sm);
        CPCOMMIT();

        const uint32_t stage = sm + (uint32_t)(kt & 3) * GM_STAGE;
#pragma unroll
        for (int k8 = 0; k8 < 2; k8++) {
            uint32_t a[4][4], bt[4][4];
#pragma unroll
            for (int i = 0; i < 4; i++)
                LDSM4(a[i], stage + a_off[i] + k8 * 32);
#pragma unroll
            for (int jp = 0; jp < 4; jp++)
                LDSM4(bt[jp], stage + b_off[jp] + k8 * 32);
#pragma unroll
            for (int i = 0; i < 4; i++)
#pragma unroll
                for (int j = 0; j < 8; j++) {
                    const int jp = j >> 1, sel = j & 1;
                    MMA_TF32(acc[i][j], a[i], bt[jp][sel], bt[jp][sel + 2]);
                }
        }
    }
}

/* ------------------------------------------------------------------ */
__global__ void __launch_bounds__(128, 2)
qkv_tc3_kernel()
{
    extern __shared__ __align__(16) float smem[];
    const uint32_t sm = smem_u32_of(smem);
    const int which = blockIdx.z;
    const float* __restrict__ Wt = (which == 0) ? g_wq : ((which == 1) ? g_wk : g_wv);
    float* __restrict__ dst = (which == 0) ? g_q : ((which == 1) ? g_k : g_v);
    const int row0 = blockIdx.y * 128, col0 = blockIdx.x * 128;

    float acc[4][8][4];
#pragma unroll
    for (int i = 0; i < 4; i++)
#pragma unroll
        for (int j = 0; j < 8; j++)
#pragma unroll
            for (int c = 0; c < 4; c++) acc[i][j][c] = 0.f;

    gemm_tc3(g_x, Wt, row0, col0, sm, acc);

    const int lane = threadIdx.x & 31, warp = threadIdx.x >> 5;
    const int wm = warp >> 1, wn = warp & 1;
    const int ar = lane >> 2, ac = lane & 3;
    const int h = (col0 >> 6) + wn;     /* warp n-tile 64 == one head */
    const bool rope = (which < 2);

    float freqs[8];
    if (rope) {
#pragma unroll
        for (int j = 0; j < 8; j++)
            freqs[j] = exp2f(-(float)(j * 4 + ac) * ROPE_LOG2C);
    }

#pragma unroll
    for (int i = 0; i < 4; i++) {
#pragma unroll
        for (int half = 0; half < 2; half++) {
            const int row = row0 + wm * 64 + i * 16 + ar + half * 8;
            const int b_ = row >> 11, s = row & (SS - 1);
            float* drow = dst + ((size_t)(b_ * HH + h) * SS + s) * DHD;
            const float sf = (float)s;
#pragma unroll
            for (int j = 0; j < 8; j++) {
                const int dh = j * 8 + 2 * ac;
                const float e = acc[i][j][half * 2], o = acc[i][j][half * 2 + 1];
                float2 w2;
                if (rope) {
                    float sn, cs;
                    sincosf(sf * freqs[j], &sn, &cs);
                    w2 = make_float2(tf32f(e * cs - o * sn), tf32f(e * sn + o * cs));
                } else {
                    w2 = make_float2(tf32f(e), tf32f(o));
                }
                *reinterpret_cast<float2*>(&drow[dh]) = w2;
            }
        }
    }
}

/* ------------------------------------------------------------------ */
__global__ void __launch_bounds__(128, 2)
out_tc3_kernel(const float* __restrict__ bo, float* __restrict__ out)
{
    extern __shared__ __align__(16) float smem[];
    const uint32_t sm = smem_u32_of(smem);
    const int row0 = blockIdx.y * 128, col0 = blockIdx.x * 128;

    float acc[4][8][4];
#pragma unroll
    for (int i = 0; i < 4; i++)
#pragma unroll
        for (int j = 0; j < 8; j++)
#pragma unroll
            for (int c = 0; c < 4; c++) acc[i][j][c] = 0.f;

    gemm_tc3(g_ctx, g_wo, row0, col0, sm, acc);

    const int lane = threadIdx.x & 31, warp = threadIdx.x >> 5;
    const int wm = warp >> 1, wn = warp & 1;
    const int ar = lane >> 2, ac = lane & 3;

#pragma unroll
    for (int i = 0; i < 4; i++) {
        const int r = row0 + wm * 64 + i * 16 + ar;
#pragma unroll
        for (int j = 0; j < 8; j++) {
            const int col = col0 + wn * 64 + j * 8 + 2 * ac;
            const float bx = bo[col], by = bo[col + 1];
            *reinterpret_cast<float2*>(&out[(size_t)r * DD + col]) =
                make_float2(acc[i][j][0] + bx, acc[i][j][1] + by);
            *reinterpret_cast<float2*>(&out[(size_t)(r + 8) * DD + col]) =
                make_float2(acc[i][j][2] + bx, acc[i][j][3] + by);
        }
    }
}

/* ================================================================== */
/* Flash attention (R5 version + exp2-domain softmax).                */
/* q-tile 128, k-tile 64, 4 warps x 32 q-rows, scalar frag loads.     */
/* ================================================================== */
#define AT_QPAD 68
#define AT_KPAD 68
#define AT_VPAD 72
#define AT_QP_BYTES (128*AT_QPAD*4)   /* 34816 */
#define AT_K_BYTES  (64*AT_KPAD*4)    /* 17408 */
#define AT_V_BYTES  (64*AT_VPAD*4)    /* 18432 */
#define AT_KOFF     AT_QP_BYTES
#define AT_VOFF     (AT_QP_BYTES + 2*AT_K_BYTES)
#define AT_SMEM     (AT_QP_BYTES + 2*AT_K_BYTES + 2*AT_V_BYTES)  /* 106496 */

__global__ void __launch_bounds__(128, 2)
attn_tc2_kernel()
{
    extern __shared__ __align__(16) float smem[];
    const uint32_t sm = smem_u32_of(smem);
    const int bh = blockIdx.y;
    const int qt = gridDim.x - 1 - blockIdx.x;   /* heavy-first */
    const float* __restrict__ Q = g_q + (size_t)bh * SS * DHD;
    const float* __restrict__ K = g_k + (size_t)bh * SS * DHD;
    const float* __restrict__ V = g_v + (size_t)bh * SS * DHD;

    const int tid = threadIdx.x;
    const int lane = tid & 31, warp = tid >> 5;
    const int ar = lane >> 2, ac = lane & 3;
    const int nk = 2 * qt + 2;

    auto issue_kv = [&](int kt, int buf) {
#pragma unroll
        for (int it = 0; it < 8; it++) {
            const int idx = tid + it * 128;
            const int r = idx >> 4, q = idx & 15;
            CP16(sm + (uint32_t)(AT_KOFF + buf * AT_K_BYTES + r * (AT_KPAD*4) + q * 16),
                 K + (size_t)(kt * 64 + r) * DHD + q * 4);
            CP16(sm + (uint32_t)(AT_VOFF + buf * AT_V_BYTES + r * (AT_VPAD*4) + q * 16),
                 V + (size_t)(kt * 64 + r) * DHD + q * 4);
        }
    };

#pragma unroll
    for (int it = 0; it < 16; it++) {
        const int idx = tid + it * 128;
        const int r = idx >> 4, q = idx & 15;
        CP16(sm + (uint32_t)(r * (AT_QPAD*4) + q * 16),
             Q + (size_t)(qt * 128 + r) * DHD + q * 4);
    }
    issue_kv(0, 0);
    CPCOMMIT();
    issue_kv(1, 1);
    CPCOMMIT();

    CPWAIT(1);
    __syncthreads();

    /* Q fragments -> registers (warp-private rows) */
    uint32_t qf[2][8][4];
    {
        const float* Qs = smem;
#pragma unroll
        for (int i = 0; i < 2; i++) {
            const int r = warp * 32 + i * 16 + ar;
#pragma unroll
            for (int k8 = 0; k8 < 8; k8++) {
                qf[i][k8][0] = __float_as_uint(Qs[r * AT_QPAD + k8 * 8 + ac]);
                qf[i][k8][1] = __float_as_uint(Qs[(r + 8) * AT_QPAD + k8 * 8 + ac]);
                qf[i][k8][2] = __float_as_uint(Qs[r * AT_QPAD + k8 * 8 + ac + 4]);
                qf[i][k8][3] = __float_as_uint(Qs[(r + 8) * AT_QPAD + k8 * 8 + ac + 4]);
            }
        }
    }

    float m[2][2], l[2][2], o[2][8][4];
#pragma unroll
    for (int i = 0; i < 2; i++) {
        m[i][0] = m[i][1] = -1e30f;
        l[i][0] = l[i][1] = 0.f;
#pragma unroll
        for (int j = 0; j < 8; j++)
#pragma unroll
            for (int c = 0; c < 4; c++) o[i][j][c] = 0.f;
    }

    float* Ps = smem;   /* reuse Q region for P (warp-private rows) */

    for (int kt = 0; kt < nk; kt++) {
        CPWAIT(1);
        __syncthreads();
        const int buf = kt & 1;
        const float* Ks = smem + (AT_KOFF + buf * AT_K_BYTES) / 4;
        const float* Vs = smem + (AT_VOFF + buf * AT_V_BYTES) / 4;

        /* ---- S = Q K^T ---- */
        float s[2][8][4];
#pragma unroll
        for (int i = 0; i < 2; i++)
#pragma unroll
            for (int j = 0; j < 8; j++)
#pragma unroll
                for (int c = 0; c < 4; c++) s[i][j][c] = 0.f;

#pragma unroll
        for (int k8 = 0; k8 < 8; k8++) {
#pragma unroll
            for (int j = 0; j < 8; j++) {
                uint32_t kb0, kb1;
                kb0 = __float_as_uint(Ks[(j * 8 + ar) * AT_KPAD + k8 * 8 + ac]);
                kb1 = __float_as_uint(Ks[(j * 8 + ar) * AT_KPAD + k8 * 8 + ac + 4]);
                MMA_TF32(s[0][j], qf[0][k8], kb0, kb1);
                MMA_TF32(s[1][j], qf[1][k8], kb0, kb1);
            }
        }

        /* ---- scale (to log2 domain) + causal mask ---- */
        const bool domask = (kt >= 2 * qt);
        const int dshift = (kt - 2 * qt) * 64;
#pragma unroll
        for (int i = 0; i < 2; i++) {
            const int r0 = warp * 32 + i * 16 + ar, r1 = r0 + 8;
#pragma unroll
            for (int j = 0; j < 8; j++) {
                float v0 = s[i][j][0] * SM_SCALE_LOG2E, v1 = s[i][j][1] * SM_SCALE_LOG2E;
                float v2 = s[i][j][2] * SM_SCALE_LOG2E, v3 = s[i][j][3] * SM_SCALE_LOG2E;
                if (domask) {
                    const int c = j * 8 + 2 * ac + dshift;
                    if (c     > r0) v0 = -1e30f;
                    if (c + 1 > r0) v1 = -1e30f;
                    if (c     > r1) v2 = -1e30f;
                    if (c + 1 > r1) v3 = -1e30f;
                }
                s[i][j][0] = v0; s[i][j][1] = v1; s[i][j][2] = v2; s[i][j][3] = v3;
            }
        }

        /* ---- online softmax (exp2 domain) ---- */
#pragma unroll
        for (int i = 0; i < 2; i++) {
            float mx0 = -1e30f, mx1 = -1e30f;
#pragma unroll
            for (int j = 0; j < 8; j++) {
                mx0 = fmaxf(mx0, fmaxf(s[i][j][0], s[i][j][1]));
                mx1 = fmaxf(mx1, fmaxf(s[i][j][2], s[i][j][3]));
            }
            mx0 = fmaxf(mx0, __shfl_xor_sync(0xffffffffu, mx0, 1));
            mx0 = fmaxf(mx0, __shfl_xor_sync(0xffffffffu, mx0, 2));
            mx1 = fmaxf(mx1, __shfl_xor_sync(0xffffffffu, mx1, 1));
            mx1 = fmaxf(mx1, __shfl_xor_sync(0xffffffffu, mx1, 2));

            const float mn0 = fmaxf(m[i][0], mx0), mn1 = fmaxf(m[i][1], mx1);
            const float corr0 = exp2f(m[i][0] - mn0), corr1 = exp2f(m[i][1] - mn1);
            m[i][0] = mn0; m[i][1] = mn1;

            const int r0 = warp * 32 + i * 16 + ar;
            float ps0 = 0.f, ps1 = 0.f;
#pragma unroll
            for (int j = 0; j < 8; j++) {
                const float p0 = exp2f(s[i][j][0] - mn0);
                const float p1 = exp2f(s[i][j][1] - mn0);
                const float p2 = exp2f(s[i][j][2] - mn1);
                const float p3 = exp2f(s[i][j][3] - mn1);
                ps0 += p0 + p1; ps1 += p2 + p3;
                const int c = j * 8 + 2 * ac;
                *reinterpret_cast<float2*>(&Ps[r0 * AT_QPAD + c]) =
                    make_float2(tf32f(p0), tf32f(p1));
                *reinterpret_cast<float2*>(&Ps[(r0 + 8) * AT_QPAD + c]) =
                    make_float2(tf32f(p2), tf32f(p3));
            }
            ps0 += __shfl_xor_sync(0xffffffffu, ps0, 1);
            ps0 += __shfl_xor_sync(0xffffffffu, ps0, 2);
            ps1 += __shfl_xor_sync(0xffffffffu, ps1, 1);
            ps1 += __shfl_xor_sync(0xffffffffu, ps1, 2);
            l[i][0] = l[i][0] * corr0 + ps0;
            l[i][1] = l[i][1] * corr1 + ps1;
#pragma unroll
            for (int j = 0; j < 8; j++) {
                o[i][j][0] *= corr0; o[i][j][1] *= corr0;
                o[i][j][2] *= corr1; o[i][j][3] *= corr1;
            }
        }
        __syncwarp();

        /* ---- O += P V ---- */
#pragma unroll
        for (int k8 = 0; k8 < 8; k8++) {
            uint32_t pa[2][4];
#pragma unroll
            for (int i = 0; i < 2; i++) {
                const int r0 = warp * 32 + i * 16 + ar;
                pa[i][0] = __float_as_uint(Ps[r0 * AT_QPAD + k8 * 8 + ac]);
                pa[i][1] = __float_as_uint(Ps[(r0 + 8) * AT_QPAD + k8 * 8 + ac]);
                pa[i][2] = __float_as_uint(Ps[r0 * AT_QPAD + k8 * 8 + ac + 4]);
                pa[i][3] = __float_as_uint(Ps[(r0 + 8) * AT_QPAD + k8 * 8 + ac + 4]);
            }
#pragma unroll
            for (int j = 0; j < 8; j++) {
                uint32_t vb0, vb1;
                vb0 = __float_as_uint(Vs[(k8 * 8 + ac) * AT_VPAD + j * 8 + ar]);
                vb1 = __float_as_uint(Vs[(k8 * 8 + ac + 4) * AT_VPAD + j * 8 + ar]);
                MMA_TF32(o[0][j], pa[0], vb0, vb1);
                MMA_TF32(o[1][j], pa[1], vb0, vb1);
            }
        }

        __syncthreads();
        if (kt + 2 < nk) issue_kv(kt + 2, buf);
        CPCOMMIT();
    }

    /* epilogue: normalize, write ctx [B*S, D] (tf32-rounded) */
    const int b_ = bh >> 4, h = bh & (HH - 1);
#pragma unroll
    for (int i = 0; i < 2; i++) {
        const float inv0 = 1.0f / l[i][0], inv1 = 1.0f / l[i][1];
        const int r0 = qt * 128 + warp * 32 + i * 16 + ar;
        float* p0 = g_ctx + (size_t)(b_ * SS + r0) * DD + h * DHD;
        float* p1 = g_ctx + (size_t)(b_ * SS + r0 + 8) * DD + h * DHD;
#pragma unroll
        for (int j = 0; j < 8; j++) {
            const int c = j * 8 + 2 * ac;
            *reinterpret_cast<float2*>(&p0[c]) =
                make_float2(tf32f(o[i][j][0] * inv0), tf32f(o[i][j][1] * inv0));
            *reinterpret_cast<float2*>(&p1[c]) =
                make_float2(tf32f(o[i][j][2] * inv1), tf32f(o[i][j][3] * inv1));
        }
    }
}

/* ------------------------------------------------------------------ */
extern "C" void kernel_launch(void* const* d_in, const int* in_sizes, int n_in,
                              void* d_out, int out_size)
{
    (void)in_sizes; (void)n_in; (void)out_size;
    const float* x  = (const float*)d_in[0];
    const float* Wq = (const float*)d_in[1];
    const float* Wk = (const float*)d_in[2];
    const float* Wv = (const float*)d_in[3];
    const float* Wo = (const float*)d_in[4];
    const float* bo = (const float*)d_in[5];
    float* out = (float*)d_out;

    cudaFuncSetAttribute(qkv_tc3_kernel,  cudaFuncAttributeMaxDynamicSharedMemorySize, GM_SMEM);
    cudaFuncSetAttribute(out_tc3_kernel,  cudaFuncAttributeMaxDynamicSharedMemorySize, GM_SMEM);
    cudaFuncSetAttribute(attn_tc2_kernel, cudaFuncAttributeMaxDynamicSharedMemorySize, AT_SMEM);

    round_x_kernel<<<4096, 256>>>(x);
    wtrans_kernel<<<dim3(32, 32, 4), dim3(32, 8)>>>(Wq, Wk, Wv, Wo);

    dim3 gq(DD / 128, NROWS / 128, 3);
    qkv_tc3_kernel<<<gq, 128, GM_SMEM>>>();

    dim3 ga(SS / 128, BB * HH);
    attn_tc2_kernel<<<ga, 128, AT_SMEM>>>();

    dim3 go(DD / 128, NROWS / 128);
    out_tc3_kernel<<<go, 128, GM_SMEM>>>(bo, out);
}

// round 8
// speedup vs baseline: 1.1317x; 1.1177x over previous
#include <cuda_runtime.h>
#include <math.h>
#include <stdint.h>

#define BB 2
#define SS 2048
#define DD 1024
#define HH 16
#define DHD 64
#define NROWS (BB*SS)          /* 4096 */
#define ROPE_LOG2C 0.4152410118609203f   /* log2(10000)/32 */
#define SM_SCALE_LOG2E 0.1803368801111204f  /* 0.125 * log2(e) */

/* Scratch (allocation-free rule) */
__device__ float g_x[(size_t)NROWS*DD];
__device__ float g_wq[DD*DD];     /* transposed, tf32-rounded */
__device__ float g_wk[DD*DD];
__device__ float g_wv[DD*DD];
__device__ float g_wo[DD*DD];
__device__ float g_q[BB*HH*SS*DHD];        /* [b,h,s,d] */
__device__ float g_k[BB*HH*SS*DHD];        /* [b,h,s,d] */
__device__ float g_v[BB*HH*SS*DHD];        /* [b,h,s,d] */
__device__ float g_ctx[(size_t)NROWS*DD];

__device__ __forceinline__ uint32_t tf32_of(float x) {
    uint32_t u;
    asm("cvt.rna.tf32.f32 %0, %1;" : "=r"(u) : "f"(x));
    return u;
}
__device__ __forceinline__ float tf32f(float x) {
    return __uint_as_float(tf32_of(x));
}
__device__ __forceinline__ uint32_t smem_u32_of(const void* p) {
    uint32_t a;
    asm("{ .reg .u64 t; cvta.to.shared.u64 t, %1; cvt.u32.u64 %0, t; }" : "=r"(a) : "l"(p));
    return a;
}

#define MMA_TF32(c, a, b0, b1) \
    asm volatile("mma.sync.aligned.m16n8k8.row.col.f32.tf32.tf32.f32 " \
        "{%0,%1,%2,%3}, {%4,%5,%6,%7}, {%8,%9}, {%0,%1,%2,%3};" \
        : "+f"((c)[0]), "+f"((c)[1]), "+f"((c)[2]), "+f"((c)[3]) \
        : "r"((a)[0]), "r"((a)[1]), "r"((a)[2]), "r"((a)[3]), \
          "r"(b0), "r"(b1))

#define CP16(dst, src) \
    asm volatile("cp.async.cg.shared.global [%0], [%1], 16;" :: "r"(dst), "l"(src))
#define CPCOMMIT() asm volatile("cp.async.commit_group;" ::: "memory")
#define CPWAIT(n)  asm volatile("cp.async.wait_group %0;" :: "n"(n) : "memory")

/* ================================================================== */
/* Pre-pass 1: round X to tf32.                                       */
/* ================================================================== */
__global__ void round_x_kernel(const float* __restrict__ X)
{
    const size_t idx = (size_t)(blockIdx.x * 256 + threadIdx.x) * 4;
    float4 v = *reinterpret_cast<const float4*>(X + idx);
    v.x = tf32f(v.x); v.y = tf32f(v.y); v.z = tf32f(v.z); v.w = tf32f(v.w);
    *reinterpret_cast<float4*>(g_x + idx) = v;
}

/* ================================================================== */
/* Pre-pass 2: transpose + round the 4 weight matrices.               */
/* ================================================================== */
__global__ void wtrans_kernel(const float* __restrict__ Wq,
                              const float* __restrict__ Wk,
                              const float* __restrict__ Wv,
                              const float* __restrict__ Wo)
{
    __shared__ float t[32][33];
    const int z = blockIdx.z;
    const float* src = (z == 0) ? Wq : ((z == 1) ? Wk : ((z == 2) ? Wv : Wo));
    float* dst = (z == 0) ? g_wq : ((z == 1) ? g_wk : ((z == 2) ? g_wv : g_wo));
    const int r0 = blockIdx.y * 32, c0 = blockIdx.x * 32;
    const int tx = threadIdx.x, ty = threadIdx.y;
#pragma unroll
    for (int k = 0; k < 4; k++)
        t[ty + 8 * k][tx] = tf32f(src[(size_t)(r0 + ty + 8 * k) * DD + c0 + tx]);
    __syncthreads();
#pragma unroll
    for (int k = 0; k < 4; k++)
        dst[(size_t)(c0 + ty + 8 * k) * DD + r0 + tx] = t[tx][ty + 8 * k];
}

/* ================================================================== */
/* GEMM: CTA 128x128, 4 warps (64x64), BK=32, cp.async x3 stages.     */
/* Both A and B (transposed weights) stored [row][k32] pitch 36.      */
/* ================================================================== */
#define GM_PITCH  36
#define GM_ABYTES (128*GM_PITCH*4)          /* 18432 */
#define GM_STAGE  (2*GM_ABYTES)             /* 36864 */
#define GM_SMEM   (3 * GM_STAGE)            /* 110592 */

__device__ __forceinline__ void gemm_issue_stage(
    const float* __restrict__ A, const float* __restrict__ Wt,
    int row0, int col0, int s, int buf, uint32_t sm)
{
    const int tid = threadIdx.x;
    const uint32_t base = sm + (uint32_t)buf * GM_STAGE;
    const int r = tid >> 3, q = tid & 7;      /* 16 rows/pass, 8 float4 per row */
#pragma unroll
    for (int it = 0; it < 8; it++) {
        const int rr = r + it * 16;
        CP16(base + (uint32_t)(rr * GM_PITCH + q * 4) * 4,
             A + (size_t)(row0 + rr) * DD + s * 32 + q * 4);
        CP16(base + GM_ABYTES + (uint32_t)(rr * GM_PITCH + q * 4) * 4,
             Wt + (size_t)(col0 + rr) * DD + s * 32 + q * 4);
    }
}

__device__ __forceinline__ void gemm_tc4(
    const float* __restrict__ A, const float* __restrict__ Wt,
    int row0, int col0, float* smem, uint32_t sm, float acc[4][8][4])
{
    const int lane = threadIdx.x & 31, warp = threadIdx.x >> 5;
    const int wm = warp >> 1, wn = warp & 1;
    const int ar = lane >> 2, ac = lane & 3;

    gemm_issue_stage(A, Wt, row0, col0, 0, 0, sm); CPCOMMIT();
    gemm_issue_stage(A, Wt, row0, col0, 1, 1, sm); CPCOMMIT();

    int cb = 0, ib = 2;   /* compute buf, issue buf */
    for (int kt = 0; kt < 32; kt++) {
        CPWAIT(1);
        __syncthreads();
        if (kt + 2 < 32) gemm_issue_stage(A, Wt, row0, col0, kt + 2, ib, sm);
        CPCOMMIT();
        if (++ib == 3) ib = 0;

        const float* As = smem + (size_t)cb * (GM_STAGE / 4);
        const float* Bs = As + GM_ABYTES / 4;
        if (++cb == 3) cb = 0;

#pragma unroll
        for (int k8 = 0; k8 < 4; k8++) {
            uint32_t a[4][4], b[8][2];
#pragma unroll
            for (int i = 0; i < 4; i++) {
                const int m = wm * 64 + i * 16 + ar;
                a[i][0] = __float_as_uint(As[m * GM_PITCH + k8 * 8 + ac]);
                a[i][1] = __float_as_uint(As[(m + 8) * GM_PITCH + k8 * 8 + ac]);
                a[i][2] = __float_as_uint(As[m * GM_PITCH + k8 * 8 + ac + 4]);
                a[i][3] = __float_as_uint(As[(m + 8) * GM_PITCH + k8 * 8 + ac + 4]);
            }
#pragma unroll
            for (int j = 0; j < 8; j++) {
                const int n = wn * 64 + j * 8 + ar;
                b[j][0] = __float_as_uint(Bs[n * GM_PITCH + k8 * 8 + ac]);
                b[j][1] = __float_as_uint(Bs[n * GM_PITCH + k8 * 8 + ac + 4]);
            }
#pragma unroll
            for (int i = 0; i < 4; i++)
#pragma unroll
                for (int j = 0; j < 8; j++)
                    MMA_TF32(acc[i][j], a[i], b[j][0], b[j][1]);
        }
    }
}

/* ------------------------------------------------------------------ */
__global__ void __launch_bounds__(128, 2)
qkv_tc4_kernel()
{
    extern __shared__ __align__(16) float smem[];
    const uint32_t sm = smem_u32_of(smem);
    const int which = blockIdx.z;
    const float* __restrict__ Wt = (which == 0) ? g_wq : ((which == 1) ? g_wk : g_wv);
    float* __restrict__ dst = (which == 0) ? g_q : ((which == 1) ? g_k : g_v);
    const int row0 = blockIdx.y * 128, col0 = blockIdx.x * 128;

    float acc[4][8][4];
#pragma unroll
    for (int i = 0; i < 4; i++)
#pragma unroll
        for (int j = 0; j < 8; j++)
#pragma unroll
            for (int c = 0; c < 4; c++) acc[i][j][c] = 0.f;

    gemm_tc4(g_x, Wt, row0, col0, smem, sm, acc);

    const int lane = threadIdx.x & 31, warp = threadIdx.x >> 5;
    const int wm = warp >> 1, wn = warp & 1;
    const int ar = lane >> 2, ac = lane & 3;
    const int h = (col0 >> 6) + wn;     /* warp n-tile 64 == one head */
    const bool rope = (which < 2);

    float freqs[8];
    if (rope) {
#pragma unroll
        for (int j = 0; j < 8; j++)
            freqs[j] = exp2f(-(float)(j * 4 + ac) * ROPE_LOG2C);
    }

#pragma unroll
    for (int i = 0; i < 4; i++) {
#pragma unroll
        for (int half = 0; half < 2; half++) {
            const int row = row0 + wm * 64 + i * 16 + ar + half * 8;
            const int b_ = row >> 11, s = row & (SS - 1);
            float* drow = dst + ((size_t)(b_ * HH + h) * SS + s) * DHD;
            const float sf = (float)s;
#pragma unroll
            for (int j = 0; j < 8; j++) {
                const int dh = j * 8 + 2 * ac;
                const float e = acc[i][j][half * 2], o = acc[i][j][half * 2 + 1];
                float2 w2;
                if (rope) {
                    float sn, cs;
                    sincosf(sf * freqs[j], &sn, &cs);
                    w2 = make_float2(tf32f(e * cs - o * sn), tf32f(e * sn + o * cs));
                } else {
                    w2 = make_float2(tf32f(e), tf32f(o));
                }
                *reinterpret_cast<float2*>(&drow[dh]) = w2;
            }
        }
    }
}

/* ------------------------------------------------------------------ */
__global__ void __launch_bounds__(128, 2)
out_tc4_kernel(const float* __restrict__ bo, float* __restrict__ out)
{
    extern __shared__ __align__(16) float smem[];
    const uint32_t sm = smem_u32_of(smem);
    const int row0 = blockIdx.y * 128, col0 = blockIdx.x * 128;

    float acc[4][8][4];
#pragma unroll
    for (int i = 0; i < 4; i++)
#pragma unroll
        for (int j = 0; j < 8; j++)
#pragma unroll
            for (int c = 0; c < 4; c++) acc[i][j][c] = 0.f;

    gemm_tc4(g_ctx, g_wo, row0, col0, smem, sm, acc);

    const int lane = threadIdx.x & 31, warp = threadIdx.x >> 5;
    const int wm = warp >> 1, wn = warp & 1;
    const int ar = lane >> 2, ac = lane & 3;

#pragma unroll
    for (int i = 0; i < 4; i++) {
        const int r = row0 + wm * 64 + i * 16 + ar;
#pragma unroll
        for (int j = 0; j < 8; j++) {
            const int col = col0 + wn * 64 + j * 8 + 2 * ac;
            const float bx = bo[col], by = bo[col + 1];
            *reinterpret_cast<float2*>(&out[(size_t)r * DD + col]) =
                make_float2(acc[i][j][0] + bx, acc[i][j][1] + by);
            *reinterpret_cast<float2*>(&out[(size_t)(r + 8) * DD + col]) =
                make_float2(acc[i][j][2] + bx, acc[i][j][3] + by);
        }
    }
}

/* ================================================================== */
/* Flash attention v4: q-tile 64, k-tile 64, 4 warps x 16 q-rows.     */
/* ~140 regs (no spills). cp.async double-buffered K/V, exp2 softmax. */
/* ================================================================== */
#define AT_QPAD 68
#define AT_KPAD 68
#define AT_VPAD 72
#define AT_QP_BYTES (64*AT_QPAD*4)    /* 17408 */
#define AT_K_BYTES  (64*AT_KPAD*4)    /* 17408 */
#define AT_V_BYTES  (64*AT_VPAD*4)    /* 18432 */
#define AT_KOFF     AT_QP_BYTES
#define AT_VOFF     (AT_QP_BYTES + 2*AT_K_BYTES)
#define AT_SMEM     (AT_QP_BYTES + 2*AT_K_BYTES + 2*AT_V_BYTES)  /* 89088 */

__global__ void __launch_bounds__(128, 2)
attn_tc4_kernel()
{
    extern __shared__ __align__(16) float smem[];
    const uint32_t sm = smem_u32_of(smem);
    const int bh = blockIdx.y;
    const int qt = gridDim.x - 1 - blockIdx.x;   /* heavy-first */
    const float* __restrict__ Q = g_q + (size_t)bh * SS * DHD;
    const float* __restrict__ K = g_k + (size_t)bh * SS * DHD;
    const float* __restrict__ V = g_v + (size_t)bh * SS * DHD;

    const int tid = threadIdx.x;
    const int lane = tid & 31, warp = tid >> 5;
    const int ar = lane >> 2, ac = lane & 3;
    const int nk = qt + 1;
    const int mrow = warp * 16;

    auto issue_kv = [&](int kt, int buf) {
#pragma unroll
        for (int it = 0; it < 8; it++) {
            const int idx = tid + it * 128;
            const int r = idx >> 4, q = idx & 15;
            CP16(sm + (uint32_t)(AT_KOFF + buf * AT_K_BYTES + r * (AT_KPAD*4) + q * 16),
                 K + (size_t)(kt * 64 + r) * DHD + q * 4);
            CP16(sm + (uint32_t)(AT_VOFF + buf * AT_V_BYTES + r * (AT_VPAD*4) + q * 16),
                 V + (size_t)(kt * 64 + r) * DHD + q * 4);
        }
    };

    /* prologue: Q + KV0 (group), KV1 (group) */
#pragma unroll
    for (int it = 0; it < 8; it++) {
        const int idx = tid + it * 128;
        const int r = idx >> 4, q = idx & 15;
        CP16(sm + (uint32_t)(r * (AT_QPAD*4) + q * 16),
             Q + (size_t)(qt * 64 + r) * DHD + q * 4);
    }
    issue_kv(0, 0);
    CPCOMMIT();
    issue_kv(nk > 1 ? 1 : 0, 1);   /* qt=0: harmless refetch of tile 0 */
    CPCOMMIT();

    CPWAIT(1);
    __syncthreads();

    /* Q fragments -> registers (warp-private 16 rows) */
    uint32_t qf[8][4];
    {
        const float* Qs = smem;
        const int r = mrow + ar;
#pragma unroll
        for (int k8 = 0; k8 < 8; k8++) {
            qf[k8][0] = __float_as_uint(Qs[r * AT_QPAD + k8 * 8 + ac]);
            qf[k8][1] = __float_as_uint(Qs[(r + 8) * AT_QPAD + k8 * 8 + ac]);
            qf[k8][2] = __float_as_uint(Qs[r * AT_QPAD + k8 * 8 + ac + 4]);
            qf[k8][3] = __float_as_uint(Qs[(r + 8) * AT_QPAD + k8 * 8 + ac + 4]);
        }
    }

    float m0 = -1e30f, m1 = -1e30f, l0 = 0.f, l1 = 0.f;
    float o[8][4];
#pragma unroll
    for (int j = 0; j < 8; j++)
#pragma unroll
        for (int c = 0; c < 4; c++) o[j][c] = 0.f;

    float* Ps = smem;   /* reuse Q region for P (warp-private rows) */

    for (int kt = 0; kt < nk; kt++) {
        CPWAIT(1);
        __syncthreads();
        const int buf = kt & 1;
        const float* Ks = smem + (AT_KOFF + buf * AT_K_BYTES) / 4;
        const float* Vs = smem + (AT_VOFF + buf * AT_V_BYTES) / 4;

        /* ---- S = Q K^T ---- */
        float s[8][4];
#pragma unroll
        for (int j = 0; j < 8; j++)
#pragma unroll
            for (int c = 0; c < 4; c++) s[j][c] = 0.f;

#pragma unroll
        for (int k8 = 0; k8 < 8; k8++) {
#pragma unroll
            for (int j = 0; j < 8; j++) {
                const uint32_t kb0 = __float_as_uint(Ks[(j * 8 + ar) * AT_KPAD + k8 * 8 + ac]);
                const uint32_t kb1 = __float_as_uint(Ks[(j * 8 + ar) * AT_KPAD + k8 * 8 + ac + 4]);
                MMA_TF32(s[j], qf[k8], kb0, kb1);
            }
        }

        /* ---- scale (log2 domain) + causal mask on diagonal ---- */
        const bool diag = (kt == qt);
        const int r0 = mrow + ar, r1 = r0 + 8;
#pragma unroll
        for (int j = 0; j < 8; j++) {
            float v0 = s[j][0] * SM_SCALE_LOG2E, v1 = s[j][1] * SM_SCALE_LOG2E;
            float v2 = s[j][2] * SM_SCALE_LOG2E, v3 = s[j][3] * SM_SCALE_LOG2E;
            if (diag) {
                const int c = j * 8 + 2 * ac;
                if (c     > r0) v0 = -1e30f;
                if (c + 1 > r0) v1 = -1e30f;
                if (c     > r1) v2 = -1e30f;
                if (c + 1 > r1) v3 = -1e30f;
            }
            s[j][0] = v0; s[j][1] = v1; s[j][2] = v2; s[j][3] = v3;
        }

        /* ---- online softmax (exp2 domain) ---- */
        float mx0 = -1e30f, mx1 = -1e30f;
#pragma unroll
        for (int j = 0; j < 8; j++) {
            mx0 = fmaxf(mx0, fmaxf(s[j][0], s[j][1]));
            mx1 = fmaxf(mx1, fmaxf(s[j][2], s[j][3]));
        }
        mx0 = fmaxf(mx0, __shfl_xor_sync(0xffffffffu, mx0, 1));
        mx0 = fmaxf(mx0, __shfl_xor_sync(0xffffffffu, mx0, 2));
        mx1 = fmaxf(mx1, __shfl_xor_sync(0xffffffffu, mx1, 1));
        mx1 = fmaxf(mx1, __shfl_xor_sync(0xffffffffu, mx1, 2));

        const float mn0 = fmaxf(m0, mx0), mn1 = fmaxf(m1, mx1);
        const float corr0 = exp2f(m0 - mn0), corr1 = exp2f(m1 - mn1);
        m0 = mn0; m1 = mn1;

        float ps0 = 0.f, ps1 = 0.f;
#pragma unroll
        for (int j = 0; j < 8; j++) {
            const float p0 = exp2f(s[j][0] - mn0);
            const float p1 = exp2f(s[j][1] - mn0);
            const float p2 = exp2f(s[j][2] - mn1);
            const float p3 = exp2f(s[j][3] - mn1);
            ps0 += p0 + p1; ps1 += p2 + p3;
            const int c = j * 8 + 2 * ac;
            *reinterpret_cast<float2*>(&Ps[r0 * AT_QPAD + c]) =
                make_float2(tf32f(p0), tf32f(p1));
            *reinterpret_cast<float2*>(&Ps[r1 * AT_QPAD + c]) =
                make_float2(tf32f(p2), tf32f(p3));
        }
        ps0 += __shfl_xor_sync(0xffffffffu, ps0, 1);
        ps0 += __shfl_xor_sync(0xffffffffu, ps0, 2);
        ps1 += __shfl_xor_sync(0xffffffffu, ps1, 1);
        ps1 += __shfl_xor_sync(0xffffffffu, ps1, 2);
        l0 = l0 * corr0 + ps0;
        l1 = l1 * corr1 + ps1;
#pragma unroll
        for (int j = 0; j < 8; j++) {
            o[j][0] *= corr0; o[j][1] *= corr0;
            o[j][2] *= corr1; o[j][3] *= corr1;
        }
        __syncwarp();

        /* ---- O += P V ---- */
#pragma unroll
        for (int k8 = 0; k8 < 8; k8++) {
            uint32_t pa[4];
            pa[0] = __float_as_uint(Ps[r0 * AT_QPAD + k8 * 8 + ac]);
            pa[1] = __float_as_uint(Ps[r1 * AT_QPAD + k8 * 8 + ac]);
            pa[2] = __float_as_uint(Ps[r0 * AT_QPAD + k8 * 8 + ac + 4]);
            pa[3] = __float_as_uint(Ps[r1 * AT_QPAD + k8 * 8 + ac + 4]);
#pragma unroll
            for (int j = 0; j < 8; j++) {
                const uint32_t vb0 = __float_as_uint(Vs[(k8 * 8 + ac) * AT_VPAD + j * 8 + ar]);
                const uint32_t vb1 = __float_as_uint(Vs[(k8 * 8 + ac + 4) * AT_VPAD + j * 8 + ar]);
                MMA_TF32(o[j], pa, vb0, vb1);
            }
        }

        __syncthreads();
        if (kt + 2 < nk) issue_kv(kt + 2, buf);
        CPCOMMIT();
    }

    /* epilogue: normalize, write ctx [B*S, D] (tf32-rounded) */
    const int b_ = bh >> 4, h = bh & (HH - 1);
    const float inv0 = 1.0f / l0, inv1 = 1.0f / l1;
    const int s0 = qt * 64 + mrow + ar, s1 = s0 + 8;
    float* p0 = g_ctx + (size_t)(b_ * SS + s0) * DD + h * DHD;
    float* p1 = g_ctx + (size_t)(b_ * SS + s1) * DD + h * DHD;
#pragma unroll
    for (int j = 0; j < 8; j++) {
        const int c = j * 8 + 2 * ac;
        *reinterpret_cast<float2*>(&p0[c]) =
            make_float2(tf32f(o[j][0] * inv0), tf32f(o[j][1] * inv0));
        *reinterpret_cast<float2*>(&p1[c]) =
            make_float2(tf32f(o[j][2] * inv1), tf32f(o[j][3] * inv1));
    }
}

/* ------------------------------------------------------------------ */
extern "C" void kernel_launch(void* const* d_in, const int* in_sizes, int n_in,
                              void* d_out, int out_size)
{
    (void)in_sizes; (void)n_in; (void)out_size;
    const float* x  = (const float*)d_in[0];
    const float* Wq = (const float*)d_in[1];
    const float* Wk = (const float*)d_in[2];
    const float* Wv = (const float*)d_in[3];
    const float* Wo = (const float*)d_in[4];
    const float* bo = (const float*)d_in[5];
    float* out = (float*)d_out;

    cudaFuncSetAttribute(qkv_tc4_kernel,  cudaFuncAttributeMaxDynamicSharedMemorySize, GM_SMEM);
    cudaFuncSetAttribute(out_tc4_kernel,  cudaFuncAttributeMaxDynamicSharedMemorySize, GM_SMEM);
    cudaFuncSetAttribute(attn_tc4_kernel, cudaFuncAttributeMaxDynamicSharedMemorySize, AT_SMEM);

    round_x_kernel<<<4096, 256>>>(x);
    wtrans_kernel<<<dim3(32, 32, 4), dim3(32, 8)>>>(Wq, Wk, Wv, Wo);

    dim3 gq(DD / 128, NROWS / 128, 3);
    qkv_tc4_kernel<<<gq, 128, GM_SMEM>>>();

    dim3 ga(SS / 64, BB * HH);
    attn_tc4_kernel<<<ga, 128, AT_SMEM>>>();

    dim3 go(DD / 128, NROWS / 128);
    out_tc4_kernel<<<go, 128, GM_SMEM>>>(bo, out);
}

// round 9
// speedup vs baseline: 1.8880x; 1.6683x over previous
#include <cuda_runtime.h>
#include <cuda_fp16.h>
#include <math.h>
#include <stdint.h>

#define BB 2
#define SS 2048
#define DD 1024
#define HH 16
#define DHD 64
#define NROWS (BB*SS)          /* 4096 */
#define ROPE_LOG2C 0.4152410118609203f   /* log2(10000)/32 */
#define SM_SCALE_LOG2E 0.1803368801111204f  /* 0.125 * log2(e) */

/* Scratch (allocation-free rule) — all fp16 now */
__device__ __half g_xh[(size_t)NROWS*DD];
__device__ __half g_wq[DD*DD];     /* transposed, fp16 */
__device__ __half g_wk[DD*DD];
__device__ __half g_wv[DD*DD];
__device__ __half g_wo[DD*DD];
__device__ __half g_q[BB*HH*SS*DHD];       /* [b,h,s,d] */
__device__ __half g_k[BB*HH*SS*DHD];       /* [b,h,s,d] */
__device__ __half g_v[BB*HH*SS*DHD];       /* [b,h,d,s] TRANSPOSED */
__device__ __half g_ctx[(size_t)NROWS*DD]; /* [b*s, d]  */

__device__ __forceinline__ uint32_t smem_u32_of(const void* p) {
    uint32_t a;
    asm("{ .reg .u64 t; cvta.to.shared.u64 t, %1; cvt.u32.u64 %0, t; }" : "=r"(a) : "l"(p));
    return a;
}
__device__ __forceinline__ uint32_t ldh2(const __half* p) {
    return *reinterpret_cast<const uint32_t*>(p);
}

#define MMA_F16(c, a, b0, b1) \
    asm volatile("mma.sync.aligned.m16n8k16.row.col.f32.f16.f16.f32 " \
        "{%0,%1,%2,%3}, {%4,%5,%6,%7}, {%8,%9}, {%0,%1,%2,%3};" \
        : "+f"((c)[0]), "+f"((c)[1]), "+f"((c)[2]), "+f"((c)[3]) \
        : "r"((a)[0]), "r"((a)[1]), "r"((a)[2]), "r"((a)[3]), \
          "r"(b0), "r"(b1))

#define CP16(dst, src) \
    asm volatile("cp.async.cg.shared.global [%0], [%1], 16;" :: "r"(dst), "l"(src))
#define CPCOMMIT() asm volatile("cp.async.commit_group;" ::: "memory")
#define CPWAIT(n)  asm volatile("cp.async.wait_group %0;" :: "n"(n) : "memory")

/* ================================================================== */
/* Pre-pass 1: X -> fp16. 8 floats / thread.                          */
/* ================================================================== */
__global__ void round_x_kernel(const float* __restrict__ X)
{
    const size_t idx = (size_t)(blockIdx.x * 256 + threadIdx.x) * 8;
    float4 v0 = *reinterpret_cast<const float4*>(X + idx);
    float4 v1 = *reinterpret_cast<const float4*>(X + idx + 4);
    __half2* ph = reinterpret_cast<__half2*>(g_xh + idx);
    ph[0] = __floats2half2_rn(v0.x, v0.y);
    ph[1] = __floats2half2_rn(v0.z, v0.w);
    ph[2] = __floats2half2_rn(v1.x, v1.y);
    ph[3] = __floats2half2_rn(v1.z, v1.w);
}

/* ================================================================== */
/* Pre-pass 2: transpose + fp16-convert the 4 weight matrices.        */
/* ================================================================== */
__global__ void wtrans_kernel(const float* __restrict__ Wq,
                              const float* __restrict__ Wk,
                              const float* __restrict__ Wv,
                              const float* __restrict__ Wo)
{
    __shared__ float t[32][33];
    const int z = blockIdx.z;
    const float* src = (z == 0) ? Wq : ((z == 1) ? Wk : ((z == 2) ? Wv : Wo));
    __half* dst = (z == 0) ? g_wq : ((z == 1) ? g_wk : ((z == 2) ? g_wv : g_wo));
    const int r0 = blockIdx.y * 32, c0 = blockIdx.x * 32;
    const int tx = threadIdx.x, ty = threadIdx.y;
#pragma unroll
    for (int k = 0; k < 4; k++)
        t[ty + 8 * k][tx] = src[(size_t)(r0 + ty + 8 * k) * DD + c0 + tx];
    __syncthreads();
#pragma unroll
    for (int k = 0; k < 4; k++)
        dst[(size_t)(c0 + ty + 8 * k) * DD + r0 + tx] = __float2half_rn(t[tx][ty + 8 * k]);
}

/* ================================================================== */
/* GEMM fp16: CTA 128x128, 4 warps (64x64), BK=32, cp.async x3.       */
/* A and B (transposed W) both stored [row][k32] pitch 40 halves.     */
/* ================================================================== */
#define GM_PITCH  40                        /* halves */
#define GM_ABYTES (128*GM_PITCH*2)          /* 10240 */
#define GM_STAGE  (2*GM_ABYTES)             /* 20480 */
#define GM_SMEM   (3 * GM_STAGE)            /* 61440 */

__device__ __forceinline__ void gemm_issue_stage(
    const __half* __restrict__ A, const __half* __restrict__ Wt,
    int row0, int col0, int s, int buf, uint32_t sm)
{
    const int tid = threadIdx.x;
    const uint32_t base = sm + (uint32_t)buf * GM_STAGE;
    const int r = tid >> 2, q = tid & 3;      /* 32 rows/pass, 4x16B per row */
#pragma unroll
    for (int it = 0; it < 4; it++) {
        const int rr = r + it * 32;
        CP16(base + (uint32_t)(rr * (GM_PITCH*2) + q * 16),
             A + (size_t)(row0 + rr) * DD + s * 32 + q * 8);
        CP16(base + GM_ABYTES + (uint32_t)(rr * (GM_PITCH*2) + q * 16),
             Wt + (size_t)(col0 + rr) * DD + s * 32 + q * 8);
    }
}

__device__ __forceinline__ void gemm_h(
    const __half* __restrict__ A, const __half* __restrict__ Wt,
    int row0, int col0, char* smem, uint32_t sm, float acc[4][8][4])
{
    const int lane = threadIdx.x & 31, warp = threadIdx.x >> 5;
    const int wm = warp >> 1, wn = warp & 1;
    const int ar = lane >> 2, ac = lane & 3;

    gemm_issue_stage(A, Wt, row0, col0, 0, 0, sm); CPCOMMIT();
    gemm_issue_stage(A, Wt, row0, col0, 1, 1, sm); CPCOMMIT();

    int cb = 0, ib = 2;
    for (int kt = 0; kt < 32; kt++) {
        CPWAIT(1);
        __syncthreads();
        if (kt + 2 < 32) gemm_issue_stage(A, Wt, row0, col0, kt + 2, ib, sm);
        CPCOMMIT();
        if (++ib == 3) ib = 0;

        const __half* AsH = reinterpret_cast<const __half*>(smem + (size_t)cb * GM_STAGE);
        const __half* BsH = AsH + 128 * GM_PITCH;
        if (++cb == 3) cb = 0;

#pragma unroll
        for (int k16 = 0; k16 < 2; k16++) {
            const int colb = k16 * 16 + 2 * ac;
            uint32_t a[4][4], b[8][2];
#pragma unroll
            for (int i = 0; i < 4; i++) {
                const int m = wm * 64 + i * 16 + ar;
                a[i][0] = ldh2(AsH + m * GM_PITCH + colb);
                a[i][1] = ldh2(AsH + (m + 8) * GM_PITCH + colb);
                a[i][2] = ldh2(AsH + m * GM_PITCH + colb + 8);
                a[i][3] = ldh2(AsH + (m + 8) * GM_PITCH + colb + 8);
            }
#pragma unroll
            for (int j = 0; j < 8; j++) {
                const int n = wn * 64 + j * 8 + ar;
                b[j][0] = ldh2(BsH + n * GM_PITCH + colb);
                b[j][1] = ldh2(BsH + n * GM_PITCH + colb + 8);
            }
#pragma unroll
            for (int i = 0; i < 4; i++)
#pragma unroll
                for (int j = 0; j < 8; j++)
                    MMA_F16(acc[i][j], a[i], b[j][0], b[j][1]);
        }
    }
}

/* ------------------------------------------------------------------ */
__global__ void __launch_bounds__(128, 2)
qkv_h_kernel()
{
    extern __shared__ __align__(16) char smem[];
    const uint32_t sm = smem_u32_of(smem);
    const int which = blockIdx.z;
    const __half* __restrict__ Wt = (which == 0) ? g_wq : ((which == 1) ? g_wk : g_wv);
    const int row0 = blockIdx.y * 128, col0 = blockIdx.x * 128;

    float acc[4][8][4];
#pragma unroll
    for (int i = 0; i < 4; i++)
#pragma unroll
        for (int j = 0; j < 8; j++)
#pragma unroll
            for (int c = 0; c < 4; c++) acc[i][j][c] = 0.f;

    gemm_h(g_xh, Wt, row0, col0, smem, sm, acc);

    const int lane = threadIdx.x & 31, warp = threadIdx.x >> 5;
    const int wm = warp >> 1, wn = warp & 1;
    const int ar = lane >> 2, ac = lane & 3;
    const int h = (col0 >> 6) + wn;     /* warp n-tile 64 == one head */

    if (which < 2) {
        __half* __restrict__ dst = (which == 0) ? g_q : g_k;
        float freqs[8];
#pragma unroll
        for (int j = 0; j < 8; j++)
            freqs[j] = exp2f(-(float)(j * 4 + ac) * ROPE_LOG2C);
#pragma unroll
        for (int i = 0; i < 4; i++) {
#pragma unroll
            for (int half_ = 0; half_ < 2; half_++) {
                const int row = row0 + wm * 64 + i * 16 + ar + half_ * 8;
                const int b_ = row >> 11, s = row & (SS - 1);
                __half* drow = dst + ((size_t)(b_ * HH + h) * SS + s) * DHD;
                const float sf = (float)s;
#pragma unroll
                for (int j = 0; j < 8; j++) {
                    const int dh = j * 8 + 2 * ac;
                    const float e = acc[i][j][half_ * 2], o = acc[i][j][half_ * 2 + 1];
                    float sn, cs;
                    sincosf(sf * freqs[j], &sn, &cs);
                    *reinterpret_cast<__half2*>(&drow[dh]) =
                        __floats2half2_rn(e * cs - o * sn, e * sn + o * cs);
                }
            }
        }
    } else {
        /* V: store TRANSPOSED [b,h,d,s] */
#pragma unroll
        for (int i = 0; i < 4; i++) {
#pragma unroll
            for (int half_ = 0; half_ < 2; half_++) {
                const int row = row0 + wm * 64 + i * 16 + ar + half_ * 8;
                const int b_ = row >> 11, s = row & (SS - 1);
                __half* dbase = g_v + ((size_t)(b_ * HH + h)) * DHD * SS;
#pragma unroll
                for (int j = 0; j < 8; j++) {
                    const int dh = j * 8 + 2 * ac;
                    dbase[(size_t)dh * SS + s]       = __float2half_rn(acc[i][j][half_ * 2]);
                    dbase[(size_t)(dh + 1) * SS + s] = __float2half_rn(acc[i][j][half_ * 2 + 1]);
                }
            }
        }
    }
}

/* ------------------------------------------------------------------ */
__global__ void __launch_bounds__(128, 2)
out_h_kernel(const float* __restrict__ bo, float* __restrict__ out)
{
    extern __shared__ __align__(16) char smem[];
    const uint32_t sm = smem_u32_of(smem);
    const int row0 = blockIdx.y * 128, col0 = blockIdx.x * 128;

    float acc[4][8][4];
#pragma unroll
    for (int i = 0; i < 4; i++)
#pragma unroll
        for (int j = 0; j < 8; j++)
#pragma unroll
            for (int c = 0; c < 4; c++) acc[i][j][c] = 0.f;

    gemm_h(g_ctx, g_wo, row0, col0, smem, sm, acc);

    const int lane = threadIdx.x & 31, warp = threadIdx.x >> 5;
    const int wm = warp >> 1, wn = warp & 1;
    const int ar = lane >> 2, ac = lane & 3;

#pragma unroll
    for (int i = 0; i < 4; i++) {
        const int r = row0 + wm * 64 + i * 16 + ar;
#pragma unroll
        for (int j = 0; j < 8; j++) {
            const int col = col0 + wn * 64 + j * 8 + 2 * ac;
            const float bx = bo[col], by = bo[col + 1];
            *reinterpret_cast<float2*>(&out[(size_t)r * DD + col]) =
                make_float2(acc[i][j][0] + bx, acc[i][j][1] + by);
            *reinterpret_cast<float2*>(&out[(size_t)(r + 8) * DD + col]) =
                make_float2(acc[i][j][2] + bx, acc[i][j][3] + by);
        }
    }
}

/* ================================================================== */
/* Flash attention fp16: q-tile 64, k-tile 64, 4 warps x 16 q-rows.   */
/* m16n8k16, V in [b,h,d,s], P reuses Q smem, exp2 softmax.           */
/* ================================================================== */
#define AT_PITCH  72                         /* halves */
#define AT_ROWB   (AT_PITCH*2)               /* 144 B */
#define AT_TILEB  (64*AT_ROWB)               /* 9216 */
#define AT_KOFF   AT_TILEB
#define AT_VOFF   (3*AT_TILEB)
#define AT_SMEM   (5*AT_TILEB)               /* 46080 */

__global__ void __launch_bounds__(128, 3)
attn_h_kernel()
{
    extern __shared__ __align__(16) char smem[];
    const uint32_t sm = smem_u32_of(smem);
    const int bh = blockIdx.y;
    const int qt = gridDim.x - 1 - blockIdx.x;   /* heavy-first */
    const __half* __restrict__ Q  = g_q + (size_t)bh * SS * DHD;
    const __half* __restrict__ K  = g_k + (size_t)bh * SS * DHD;
    const __half* __restrict__ Vt = g_v + (size_t)bh * DHD * SS;  /* [d][s] */

    const int tid = threadIdx.x;
    const int lane = tid & 31, warp = tid >> 5;
    const int ar = lane >> 2, ac = lane & 3;
    const int nk = qt + 1;
    const int mrow = warp * 16;

    auto issue_kv = [&](int kt, int buf) {
#pragma unroll
        for (int it = 0; it < 4; it++) {
            const int idx = tid + it * 128;
            const int r = idx >> 3, q = idx & 7;
            CP16(sm + (uint32_t)(AT_KOFF + buf * AT_TILEB + r * AT_ROWB + q * 16),
                 K + (size_t)(kt * 64 + r) * DHD + q * 8);
            CP16(sm + (uint32_t)(AT_VOFF + buf * AT_TILEB + r * AT_ROWB + q * 16),
                 Vt + (size_t)r * SS + kt * 64 + q * 8);
        }
    };

#pragma unroll
    for (int it = 0; it < 4; it++) {
        const int idx = tid + it * 128;
        const int r = idx >> 3, q = idx & 7;
        CP16(sm + (uint32_t)(r * AT_ROWB + q * 16),
             Q + (size_t)(qt * 64 + r) * DHD + q * 8);
    }
    issue_kv(0, 0);
    CPCOMMIT();
    issue_kv(nk > 1 ? 1 : 0, 1);
    CPCOMMIT();

    CPWAIT(1);
    __syncthreads();

    /* Q fragments -> registers */
    uint32_t qf[4][4];
    {
        const __half* Qs = reinterpret_cast<const __half*>(smem);
        const int r = mrow + ar;
#pragma unroll
        for (int k16 = 0; k16 < 4; k16++) {
            const int colb = k16 * 16 + 2 * ac;
            qf[k16][0] = ldh2(Qs + r * AT_PITCH + colb);
            qf[k16][1] = ldh2(Qs + (r + 8) * AT_PITCH + colb);
            qf[k16][2] = ldh2(Qs + r * AT_PITCH + colb + 8);
            qf[k16][3] = ldh2(Qs + (r + 8) * AT_PITCH + colb + 8);
        }
    }

    float m0 = -1e30f, m1 = -1e30f, l0 = 0.f, l1 = 0.f;
    float o[8][4];
#pragma unroll
    for (int j = 0; j < 8; j++)
#pragma unroll
        for (int c = 0; c < 4; c++) o[j][c] = 0.f;

    __half* Ph = reinterpret_cast<__half*>(smem);  /* reuse Q region for P */

    for (int kt = 0; kt < nk; kt++) {
        CPWAIT(1);
        __syncthreads();
        const int buf = kt & 1;
        const __half* Ks = reinterpret_cast<const __half*>(smem + AT_KOFF + buf * AT_TILEB);
        const __half* Vs = reinterpret_cast<const __half*>(smem + AT_VOFF + buf * AT_TILEB);

        /* ---- S = Q K^T ---- */
        float s[8][4];
#pragma unroll
        for (int j = 0; j < 8; j++)
#pragma unroll
            for (int c = 0; c < 4; c++) s[j][c] = 0.f;

#pragma unroll
        for (int k16 = 0; k16 < 4; k16++) {
            const int colb = k16 * 16 + 2 * ac;
#pragma unroll
            for (int j = 0; j < 8; j++) {
                const uint32_t kb0 = ldh2(Ks + (j * 8 + ar) * AT_PITCH + colb);
                const uint32_t kb1 = ldh2(Ks + (j * 8 + ar) * AT_PITCH + colb + 8);
                MMA_F16(s[j], qf[k16], kb0, kb1);
            }
        }

        /* ---- scale (log2 domain) + causal mask on diagonal ---- */
        const bool diag = (kt == qt);
        const int r0 = mrow + ar, r1 = r0 + 8;
#pragma unroll
        for (int j = 0; j < 8; j++) {
            float v0 = s[j][0] * SM_SCALE_LOG2E, v1 = s[j][1] * SM_SCALE_LOG2E;
            float v2 = s[j][2] * SM_SCALE_LOG2E, v3 = s[j][3] * SM_SCALE_LOG2E;
            if (diag) {
                const int c = j * 8 + 2 * ac;
                if (c     > r0) v0 = -1e30f;
                if (c + 1 > r0) v1 = -1e30f;
                if (c     > r1) v2 = -1e30f;
                if (c + 1 > r1) v3 = -1e30f;
            }
            s[j][0] = v0; s[j][1] = v1; s[j][2] = v2; s[j][3] = v3;
        }

        /* ---- online softmax (exp2 domain) ---- */
        float mx0 = -1e30f, mx1 = -1e30f;
#pragma unroll
        for (int j = 0; j < 8; j++) {
            mx0 = fmaxf(mx0, fmaxf(s[j][0], s[j][1]));
            mx1 = fmaxf(mx1, fmaxf(s[j][2], s[j][3]));
        }
        mx0 = fmaxf(mx0, __shfl_xor_sync(0xffffffffu, mx0, 1));
        mx0 = fmaxf(mx0, __shfl_xor_sync(0xffffffffu, mx0, 2));
        mx1 = fmaxf(mx1, __shfl_xor_sync(0xffffffffu, mx1, 1));
        mx1 = fmaxf(mx1, __shfl_xor_sync(0xffffffffu, mx1, 2));

        const float mn0 = fmaxf(m0, mx0), mn1 = fmaxf(m1, mx1);
        const float corr0 = exp2f(m0 - mn0), corr1 = exp2f(m1 - mn1);
        m0 = mn0; m1 = mn1;

        float ps0 = 0.f, ps1 = 0.f;
#pragma unroll
        for (int j = 0; j < 8; j++) {
            const float p0 = exp2f(s[j][0] - mn0);
            const float p1 = exp2f(s[j][1] - mn0);
            const float p2 = exp2f(s[j][2] - mn1);
            const float p3 = exp2f(s[j][3] - mn1);
            ps0 += p0 + p1; ps1 += p2 + p3;
            const int c = j * 8 + 2 * ac;
            *reinterpret_cast<__half2*>(Ph + r0 * AT_PITCH + c) = __floats2half2_rn(p0, p1);
            *reinterpret_cast<__half2*>(Ph + r1 * AT_PITCH + c) = __floats2half2_rn(p2, p3);
        }
        ps0 += __shfl_xor_sync(0xffffffffu, ps0, 1);
        ps0 += __shfl_xor_sync(0xffffffffu, ps0, 2);
        ps1 += __shfl_xor_sync(0xffffffffu, ps1, 1);
        ps1 += __shfl_xor_sync(0xffffffffu, ps1, 2);
        l0 = l0 * corr0 + ps0;
        l1 = l1 * corr1 + ps1;
#pragma unroll
        for (int j = 0; j < 8; j++) {
            o[j][0] *= corr0; o[j][1] *= corr0;
            o[j][2] *= corr1; o[j][3] *= corr1;
        }
        __syncwarp();

        /* ---- O += P V ---- */
#pragma unroll
        for (int k16 = 0; k16 < 4; k16++) {
            const int colb = k16 * 16 + 2 * ac;
            uint32_t pa[4];
            pa[0] = ldh2(Ph + r0 * AT_PITCH + colb);
            pa[1] = ldh2(Ph + r1 * AT_PITCH + colb);
            pa[2] = ldh2(Ph + r0 * AT_PITCH + colb + 8);
            pa[3] = ldh2(Ph + r1 * AT_PITCH + colb + 8);
#pragma unroll
            for (int j = 0; j < 8; j++) {
                const uint32_t vb0 = ldh2(Vs + (j * 8 + ar) * AT_PITCH + colb);
                const uint32_t vb1 = ldh2(Vs + (j * 8 + ar) * AT_PITCH + colb + 8);
                MMA_F16(o[j], pa, vb0, vb1);
            }
        }

        __syncthreads();
        if (kt + 2 < nk) issue_kv(kt + 2, buf);
        CPCOMMIT();
    }

    /* epilogue: normalize, write ctx fp16 [B*S, D] */
    const int b_ = bh >> 4, h = bh & (HH - 1);
    const float inv0 = 1.0f / l0, inv1 = 1.0f / l1;
    const int s0 = qt * 64 + mrow + ar, s1 = s0 + 8;
    __half* p0 = g_ctx + (size_t)(b_ * SS + s0) * DD + h * DHD;
    __half* p1 = g_ctx + (size_t)(b_ * SS + s1) * DD + h * DHD;
#pragma unroll
    for (int j = 0; j < 8; j++) {
        const int c = j * 8 + 2 * ac;
        *reinterpret_cast<__half2*>(&p0[c]) =
            __floats2half2_rn(o[j][0] * inv0, o[j][1] * inv0);
        *reinterpret_cast<__half2*>(&p1[c]) =
            __floats2half2_rn(o[j][2] * inv1, o[j][3] * inv1);
    }
}

/* ------------------------------------------------------------------ */
extern "C" void kernel_launch(void* const* d_in, const int* in_sizes, int n_in,
                              void* d_out, int out_size)
{
    (void)in_sizes; (void)n_in; (void)out_size;
    const float* x  = (const float*)d_in[0];
    const float* Wq = (const float*)d_in[1];
    const float* Wk = (const float*)d_in[2];
    const float* Wv = (const float*)d_in[3];
    const float* Wo = (const float*)d_in[4];
    const float* bo = (const float*)d_in[5];
    float* out = (float*)d_out;

    cudaFuncSetAttribute(qkv_h_kernel,  cudaFuncAttributeMaxDynamicSharedMemorySize, GM_SMEM);
    cudaFuncSetAttribute(out_h_kernel,  cudaFuncAttributeMaxDynamicSharedMemorySize, GM_SMEM);
    cudaFuncSetAttribute(attn_h_kernel, cudaFuncAttributeMaxDynamicSharedMemorySize, AT_SMEM);

    round_x_kernel<<<2048, 256>>>(x);
    wtrans_kernel<<<dim3(32, 32, 4), dim3(32, 8)>>>(Wq, Wk, Wv, Wo);

    dim3 gq(DD / 128, NROWS / 128, 3);
    qkv_h_kernel<<<gq, 128, GM_SMEM>>>();

    dim3 ga(SS / 64, BB * HH);
    attn_h_kernel<<<ga, 128, AT_SMEM>>>();

    dim3 go(DD / 128, NROWS / 128);
    out_h_kernel<<<go, 128, GM_SMEM>>>(bo, out);
}

// round 10
// speedup vs baseline: 1.9478x; 1.0317x over previous
#include <cuda_runtime.h>
#include <cuda_fp16.h>
#include <math.h>
#include <stdint.h>

#define BB 2
#define SS 2048
#define DD 1024
#define HH 16
#define DHD 64
#define NROWS (BB*SS)          /* 4096 */
#define ROPE_LOG2C 0.4152410118609203f   /* log2(10000)/32 */
#define SM_SCALE_LOG2E 0.1803368801111204f  /* 0.125 * log2(e) */

/* Scratch (allocation-free rule) — all fp16 */
__device__ __half g_xh[(size_t)NROWS*DD];
__device__ __half g_wq[DD*DD];     /* transposed, fp16 */
__device__ __half g_wk[DD*DD];
__device__ __half g_wv[DD*DD];
__device__ __half g_wo[DD*DD];
__device__ __half g_q[BB*HH*SS*DHD];       /* [b,h,s,d], pre-scaled by 0.125*log2e */
__device__ __half g_k[BB*HH*SS*DHD];       /* [b,h,s,d] */
__device__ __half g_v[BB*HH*SS*DHD];       /* [b,h,d,s] TRANSPOSED */
__device__ __half g_ctx[(size_t)NROWS*DD]; /* [b*s, d]  */

__device__ __forceinline__ uint32_t smem_u32_of(const void* p) {
    uint32_t a;
    asm("{ .reg .u64 t; cvta.to.shared.u64 t, %1; cvt.u32.u64 %0, t; }" : "=r"(a) : "l"(p));
    return a;
}
__device__ __forceinline__ uint32_t ldh2(const __half* p) {
    return *reinterpret_cast<const uint32_t*>(p);
}
__device__ __forceinline__ uint32_t h2pack(float a, float b) {
    __half2 h = __floats2half2_rn(a, b);
    return *reinterpret_cast<uint32_t*>(&h);
}

#define MMA_F16(c, a, b0, b1) \
    asm volatile("mma.sync.aligned.m16n8k16.row.col.f32.f16.f16.f32 " \
        "{%0,%1,%2,%3}, {%4,%5,%6,%7}, {%8,%9}, {%0,%1,%2,%3};" \
        : "+f"((c)[0]), "+f"((c)[1]), "+f"((c)[2]), "+f"((c)[3]) \
        : "r"((a)[0]), "r"((a)[1]), "r"((a)[2]), "r"((a)[3]), \
          "r"(b0), "r"(b1))

#define CP16(dst, src) \
    asm volatile("cp.async.cg.shared.global [%0], [%1], 16;" :: "r"(dst), "l"(src))
#define CPCOMMIT() asm volatile("cp.async.commit_group;" ::: "memory")
#define CPWAIT(n)  asm volatile("cp.async.wait_group %0;" :: "n"(n) : "memory")

/* ================================================================== */
/* Pre-pass 1: X -> fp16. 8 floats / thread.                          */
/* ================================================================== */
__global__ void round_x_kernel(const float* __restrict__ X)
{
    const size_t idx = (size_t)(blockIdx.x * 256 + threadIdx.x) * 8;
    float4 v0 = *reinterpret_cast<const float4*>(X + idx);
    float4 v1 = *reinterpret_cast<const float4*>(X + idx + 4);
    __half2* ph = reinterpret_cast<__half2*>(g_xh + idx);
    ph[0] = __floats2half2_rn(v0.x, v0.y);
    ph[1] = __floats2half2_rn(v0.z, v0.w);
    ph[2] = __floats2half2_rn(v1.x, v1.y);
    ph[3] = __floats2half2_rn(v1.z, v1.w);
}

/* ================================================================== */
/* Pre-pass 2: transpose + fp16-convert the 4 weight matrices.        */
/* ================================================================== */
__global__ void wtrans_kernel(const float* __restrict__ Wq,
                              const float* __restrict__ Wk,
                              const float* __restrict__ Wv,
                              const float* __restrict__ Wo)
{
    __shared__ float t[32][33];
    const int z = blockIdx.z;
    const float* src = (z == 0) ? Wq : ((z == 1) ? Wk : ((z == 2) ? Wv : Wo));
    __half* dst = (z == 0) ? g_wq : ((z == 1) ? g_wk : ((z == 2) ? g_wv : g_wo));
    const int r0 = blockIdx.y * 32, c0 = blockIdx.x * 32;
    const int tx = threadIdx.x, ty = threadIdx.y;
#pragma unroll
    for (int k = 0; k < 4; k++)
        t[ty + 8 * k][tx] = src[(size_t)(r0 + ty + 8 * k) * DD + c0 + tx];
    __syncthreads();
#pragma unroll
    for (int k = 0; k < 4; k++)
        dst[(size_t)(c0 + ty + 8 * k) * DD + r0 + tx] = __float2half_rn(t[tx][ty + 8 * k]);
}

/* ================================================================== */
/* GEMM fp16: CTA 128x128, 4 warps (64x64), BK=32, cp.async x3.       */
/* ================================================================== */
#define GM_PITCH  40                        /* halves */
#define GM_ABYTES (128*GM_PITCH*2)          /* 10240 */
#define GM_STAGE  (2*GM_ABYTES)             /* 20480 */
#define GM_SMEM   (3 * GM_STAGE)            /* 61440 */

__device__ __forceinline__ void gemm_issue_stage(
    const __half* __restrict__ A, const __half* __restrict__ Wt,
    int row0, int col0, int s, int buf, uint32_t sm)
{
    const int tid = threadIdx.x;
    const uint32_t base = sm + (uint32_t)buf * GM_STAGE;
    const int r = tid >> 2, q = tid & 3;
#pragma unroll
    for (int it = 0; it < 4; it++) {
        const int rr = r + it * 32;
        CP16(base + (uint32_t)(rr * (GM_PITCH*2) + q * 16),
             A + (size_t)(row0 + rr) * DD + s * 32 + q * 8);
        CP16(base + GM_ABYTES + (uint32_t)(rr * (GM_PITCH*2) + q * 16),
             Wt + (size_t)(col0 + rr) * DD + s * 32 + q * 8);
    }
}

__device__ __forceinline__ void gemm_h(
    const __half* __restrict__ A, const __half* __restrict__ Wt,
    int row0, int col0, char* smem, uint32_t sm, float acc[4][8][4])
{
    const int lane = threadIdx.x & 31, warp = threadIdx.x >> 5;
    const int wm = warp >> 1, wn = warp & 1;
    const int ar = lane >> 2, ac = lane & 3;

    gemm_issue_stage(A, Wt, row0, col0, 0, 0, sm); CPCOMMIT();
    gemm_issue_stage(A, Wt, row0, col0, 1, 1, sm); CPCOMMIT();

    int cb = 0, ib = 2;
    for (int kt = 0; kt < 32; kt++) {
        CPWAIT(1);
        __syncthreads();
        if (kt + 2 < 32) gemm_issue_stage(A, Wt, row0, col0, kt + 2, ib, sm);
        CPCOMMIT();
        if (++ib == 3) ib = 0;

        const __half* AsH = reinterpret_cast<const __half*>(smem + (size_t)cb * GM_STAGE);
        const __half* BsH = AsH + 128 * GM_PITCH;
        if (++cb == 3) cb = 0;

#pragma unroll
        for (int k16 = 0; k16 < 2; k16++) {
            const int colb = k16 * 16 + 2 * ac;
            uint32_t a[4][4], b[8][2];
#pragma unroll
            for (int i = 0; i < 4; i++) {
                const int m = wm * 64 + i * 16 + ar;
                a[i][0] = ldh2(AsH + m * GM_PITCH + colb);
                a[i][1] = ldh2(AsH + (m + 8) * GM_PITCH + colb);
                a[i][2] = ldh2(AsH + m * GM_PITCH + colb + 8);
                a[i][3] = ldh2(AsH + (m + 8) * GM_PITCH + colb + 8);
            }
#pragma unroll
            for (int j = 0; j < 8; j++) {
                const int n = wn * 64 + j * 8 + ar;
                b[j][0] = ldh2(BsH + n * GM_PITCH + colb);
                b[j][1] = ldh2(BsH + n * GM_PITCH + colb + 8);
            }
#pragma unroll
            for (int i = 0; i < 4; i++)
#pragma unroll
                for (int j = 0; j < 8; j++)
                    MMA_F16(acc[i][j], a[i], b[j][0], b[j][1]);
        }
    }
}

/* ------------------------------------------------------------------ */
__global__ void __launch_bounds__(128, 2)
qkv_h_kernel()
{
    extern __shared__ __align__(16) char smem[];
    const uint32_t sm = smem_u32_of(smem);
    const int which = blockIdx.z;
    const __half* __restrict__ Wt = (which == 0) ? g_wq : ((which == 1) ? g_wk : g_wv);
    const int row0 = blockIdx.y * 128, col0 = blockIdx.x * 128;

    float acc[4][8][4];
#pragma unroll
    for (int i = 0; i < 4; i++)
#pragma unroll
        for (int j = 0; j < 8; j++)
#pragma unroll
            for (int c = 0; c < 4; c++) acc[i][j][c] = 0.f;

    gemm_h(g_xh, Wt, row0, col0, smem, sm, acc);

    const int lane = threadIdx.x & 31, warp = threadIdx.x >> 5;
    const int wm = warp >> 1, wn = warp & 1;
    const int ar = lane >> 2, ac = lane & 3;
    const int h = (col0 >> 6) + wn;

    if (which < 2) {
        __half* __restrict__ dst = (which == 0) ? g_q : g_k;
        const float post = (which == 0) ? SM_SCALE_LOG2E : 1.0f;
        float freqs[8];
#pragma unroll
        for (int j = 0; j < 8; j++)
            freqs[j] = exp2f(-(float)(j * 4 + ac) * ROPE_LOG2C);
#pragma unroll
        for (int i = 0; i < 4; i++) {
#pragma unroll
            for (int half_ = 0; half_ < 2; half_++) {
                const int row = row0 + wm * 64 + i * 16 + ar + half_ * 8;
                const int b_ = row >> 11, s = row & (SS - 1);
                __half* drow = dst + ((size_t)(b_ * HH + h) * SS + s) * DHD;
                const float sf = (float)s;
#pragma unroll
                for (int j = 0; j < 8; j++) {
                    const int dh = j * 8 + 2 * ac;
                    const float e = acc[i][j][half_ * 2], o = acc[i][j][half_ * 2 + 1];
                    float sn, cs;
                    sincosf(sf * freqs[j], &sn, &cs);
                    *reinterpret_cast<__half2*>(&drow[dh]) =
                        __floats2half2_rn((e * cs - o * sn) * post,
                                          (e * sn + o * cs) * post);
                }
            }
        }
    } else {
        /* V: store TRANSPOSED [b,h,d,s] */
#pragma unroll
        for (int i = 0; i < 4; i++) {
#pragma unroll
            for (int half_ = 0; half_ < 2; half_++) {
                const int row = row0 + wm * 64 + i * 16 + ar + half_ * 8;
                const int b_ = row >> 11, s = row & (SS - 1);
                __half* dbase = g_v + ((size_t)(b_ * HH + h)) * DHD * SS;
#pragma unroll
                for (int j = 0; j < 8; j++) {
                    const int dh = j * 8 + 2 * ac;
                    dbase[(size_t)dh * SS + s]       = __float2half_rn(acc[i][j][half_ * 2]);
                    dbase[(size_t)(dh + 1) * SS + s] = __float2half_rn(acc[i][j][half_ * 2 + 1]);
                }
            }
        }
    }
}

/* ------------------------------------------------------------------ */
__global__ void __launch_bounds__(128, 2)
out_h_kernel(const float* __restrict__ bo, float* __restrict__ out)
{
    extern __shared__ __align__(16) char smem[];
    const uint32_t sm = smem_u32_of(smem);
    const int row0 = blockIdx.y * 128, col0 = blockIdx.x * 128;

    float acc[4][8][4];
#pragma unroll
    for (int i = 0; i < 4; i++)
#pragma unroll
        for (int j = 0; j < 8; j++)
#pragma unroll
            for (int c = 0; c < 4; c++) acc[i][j][c] = 0.f;

    gemm_h(g_ctx, g_wo, row0, col0, smem, sm, acc);

    const int lane = threadIdx.x & 31, warp = threadIdx.x >> 5;
    const int wm = warp >> 1, wn = warp & 1;
    const int ar = lane >> 2, ac = lane & 3;

#pragma unroll
    for (int i = 0; i < 4; i++) {
        const int r = row0 + wm * 64 + i * 16 + ar;
#pragma unroll
        for (int j = 0; j < 8; j++) {
            const int col = col0 + wn * 64 + j * 8 + 2 * ac;
            const float bx = bo[col], by = bo[col + 1];
            *reinterpret_cast<float2*>(&out[(size_t)r * DD + col]) =
                make_float2(acc[i][j][0] + bx, acc[i][j][1] + by);
            *reinterpret_cast<float2*>(&out[(size_t)(r + 8) * DD + col]) =
                make_float2(acc[i][j][2] + bx, acc[i][j][3] + by);
        }
    }
}

/* ================================================================== */
/* Flash attention fp16 v2: P kept in registers (acc->A frag remap).  */
/* q-tile 64, k-tile 64, 4 warps x 16 q-rows, exp2 softmax.           */
/* ================================================================== */
#define AT_PITCH  72                         /* halves */
#define AT_ROWB   (AT_PITCH*2)               /* 144 B */
#define AT_TILEB  (64*AT_ROWB)               /* 9216 */
#define AT_KOFF   AT_TILEB
#define AT_VOFF   (3*AT_TILEB)
#define AT_SMEM   (5*AT_TILEB)               /* 46080 */

__global__ void __launch_bounds__(128, 3)
attn_h_kernel()
{
    extern __shared__ __align__(16) char smem[];
    const uint32_t sm = smem_u32_of(smem);
    const int bh = blockIdx.y;
    const int qt = gridDim.x - 1 - blockIdx.x;   /* heavy-first */
    const __half* __restrict__ Q  = g_q + (size_t)bh * SS * DHD;
    const __half* __restrict__ K  = g_k + (size_t)bh * SS * DHD;
    const __half* __restrict__ Vt = g_v + (size_t)bh * DHD * SS;  /* [d][s] */

    const int tid = threadIdx.x;
    const int lane = tid & 31, warp = tid >> 5;
    const int ar = lane >> 2, ac = lane & 3;
    const int nk = qt + 1;
    const int mrow = warp * 16;

    auto issue_kv = [&](int kt, int buf) {
#pragma unroll
        for (int it = 0; it < 4; it++) {
            const int idx = tid + it * 128;
            const int r = idx >> 3, q = idx & 7;
            CP16(sm + (uint32_t)(AT_KOFF + buf * AT_TILEB + r * AT_ROWB + q * 16),
                 K + (size_t)(kt * 64 + r) * DHD + q * 8);
            CP16(sm + (uint32_t)(AT_VOFF + buf * AT_TILEB + r * AT_ROWB + q * 16),
                 Vt + (size_t)r * SS + kt * 64 + q * 8);
        }
    };

#pragma unroll
    for (int it = 0; it < 4; it++) {
        const int idx = tid + it * 128;
        const int r = idx >> 3, q = idx & 7;
        CP16(sm + (uint32_t)(r * AT_ROWB + q * 16),
             Q + (size_t)(qt * 64 + r) * DHD + q * 8);
    }
    issue_kv(0, 0);
    CPCOMMIT();
    issue_kv(nk > 1 ? 1 : 0, 1);
    CPCOMMIT();

    CPWAIT(1);
    __syncthreads();

    /* Q fragments -> registers */
    uint32_t qf[4][4];
    {
        const __half* Qs = reinterpret_cast<const __half*>(smem);
        const int r = mrow + ar;
#pragma unroll
        for (int k16 = 0; k16 < 4; k16++) {
            const int colb = k16 * 16 + 2 * ac;
            qf[k16][0] = ldh2(Qs + r * AT_PITCH + colb);
            qf[k16][1] = ldh2(Qs + (r + 8) * AT_PITCH + colb);
            qf[k16][2] = ldh2(Qs + r * AT_PITCH + colb + 8);
            qf[k16][3] = ldh2(Qs + (r + 8) * AT_PITCH + colb + 8);
        }
    }

    float m0 = -1e30f, m1 = -1e30f, l0 = 0.f, l1 = 0.f;
    float o[8][4];
#pragma unroll
    for (int j = 0; j < 8; j++)
#pragma unroll
        for (int c = 0; c < 4; c++) o[j][c] = 0.f;

    for (int kt = 0; kt < nk; kt++) {
        CPWAIT(1);
        __syncthreads();
        const int buf = kt & 1;
        const __half* Ks = reinterpret_cast<const __half*>(smem + AT_KOFF + buf * AT_TILEB);
        const __half* Vs = reinterpret_cast<const __half*>(smem + AT_VOFF + buf * AT_TILEB);

        /* ---- S = Q K^T  (already in log2 domain: Q pre-scaled) ---- */
        float s[8][4];
#pragma unroll
        for (int j = 0; j < 8; j++)
#pragma unroll
            for (int c = 0; c < 4; c++) s[j][c] = 0.f;

#pragma unroll
        for (int k16 = 0; k16 < 4; k16++) {
            const int colb = k16 * 16 + 2 * ac;
#pragma unroll
            for (int j = 0; j < 8; j++) {
                const uint32_t kb0 = ldh2(Ks + (j * 8 + ar) * AT_PITCH + colb);
                const uint32_t kb1 = ldh2(Ks + (j * 8 + ar) * AT_PITCH + colb + 8);
                MMA_F16(s[j], qf[k16], kb0, kb1);
            }
        }

        /* ---- causal mask on diagonal tile ---- */
        const int r0 = mrow + ar, r1 = r0 + 8;
        if (kt == qt) {
#pragma unroll
            for (int j = 0; j < 8; j++) {
                const int c = j * 8 + 2 * ac;
                if (c     > r0) s[j][0] = -1e30f;
                if (c + 1 > r0) s[j][1] = -1e30f;
                if (c     > r1) s[j][2] = -1e30f;
                if (c + 1 > r1) s[j][3] = -1e30f;
            }
        }

        /* ---- online softmax (exp2 domain), P stays in registers ---- */
        float mx0 = -1e30f, mx1 = -1e30f;
#pragma unroll
        for (int j = 0; j < 8; j++) {
            mx0 = fmaxf(mx0, fmaxf(s[j][0], s[j][1]));
            mx1 = fmaxf(mx1, fmaxf(s[j][2], s[j][3]));
        }
        mx0 = fmaxf(mx0, __shfl_xor_sync(0xffffffffu, mx0, 1));
        mx0 = fmaxf(mx0, __shfl_xor_sync(0xffffffffu, mx0, 2));
        mx1 = fmaxf(mx1, __shfl_xor_sync(0xffffffffu, mx1, 1));
        mx1 = fmaxf(mx1, __shfl_xor_sync(0xffffffffu, mx1, 2));

        const float mn0 = fmaxf(m0, mx0), mn1 = fmaxf(m1, mx1);
        const float corr0 = exp2f(m0 - mn0), corr1 = exp2f(m1 - mn1);
        m0 = mn0; m1 = mn1;

        float ps0 = 0.f, ps1 = 0.f;
#pragma unroll
        for (int j = 0; j < 8; j++) {
            s[j][0] = exp2f(s[j][0] - mn0);
            s[j][1] = exp2f(s[j][1] - mn0);
            s[j][2] = exp2f(s[j][2] - mn1);
            s[j][3] = exp2f(s[j][3] - mn1);
            ps0 += s[j][0] + s[j][1];
            ps1 += s[j][2] + s[j][3];
        }
        ps0 += __shfl_xor_sync(0xffffffffu, ps0, 1);
        ps0 += __shfl_xor_sync(0xffffffffu, ps0, 2);
        ps1 += __shfl_xor_sync(0xffffffffu, ps1, 1);
        ps1 += __shfl_xor_sync(0xffffffffu, ps1, 2);
        l0 = l0 * corr0 + ps0;
        l1 = l1 * corr1 + ps1;
#pragma unroll
        for (int j = 0; j < 8; j++) {
            o[j][0] *= corr0; o[j][1] *= corr0;
            o[j][2] *= corr1; o[j][3] *= corr1;
        }

        /* ---- O += P V  (P: acc->A-frag register remap) ---- */
#pragma unroll
        for (int k16 = 0; k16 < 4; k16++) {
            uint32_t pa[4];
            pa[0] = h2pack(s[2 * k16][0],     s[2 * k16][1]);
            pa[1] = h2pack(s[2 * k16][2],     s[2 * k16][3]);
            pa[2] = h2pack(s[2 * k16 + 1][0], s[2 * k16 + 1][1]);
            pa[3] = h2pack(s[2 * k16 + 1][2], s[2 * k16 + 1][3]);
            const int colb = k16 * 16 + 2 * ac;
#pragma unroll
            for (int j = 0; j < 8; j++) {
                const uint32_t vb0 = ldh2(Vs + (j * 8 + ar) * AT_PITCH + colb);
                const uint32_t vb1 = ldh2(Vs + (j * 8 + ar) * AT_PITCH + colb + 8);
                MMA_F16(o[j], pa, vb0, vb1);
            }
        }

        __syncthreads();
        if (kt + 2 < nk) issue_kv(kt + 2, buf);
        CPCOMMIT();
    }

    /* epilogue: normalize, write ctx fp16 [B*S, D] */
    const int b_ = bh >> 4, h = bh & (HH - 1);
    const float inv0 = 1.0f / l0, inv1 = 1.0f / l1;
    const int s0 = qt * 64 + mrow + ar, s1 = s0 + 8;
    __half* p0 = g_ctx + (size_t)(b_ * SS + s0) * DD + h * DHD;
    __half* p1 = g_ctx + (size_t)(b_ * SS + s1) * DD + h * DHD;
#pragma unroll
    for (int j = 0; j < 8; j++) {
        const int c = j * 8 + 2 * ac;
        *reinterpret_cast<__half2*>(&p0[c]) =
            __floats2half2_rn(o[j][0] * inv0, o[j][1] * inv0);
        *reinterpret_cast<__half2*>(&p1[c]) =
            __floats2half2_rn(o[j][2] * inv1, o[j][3] * inv1);
    }
}

/* ------------------------------------------------------------------ */
extern "C" void kernel_launch(void* const* d_in, const int* in_sizes, int n_in,
                              void* d_out, int out_size)
{
    (void)in_sizes; (void)n_in; (void)out_size;
    const float* x  = (const float*)d_in[0];
    const float* Wq = (const float*)d_in[1];
    const float* Wk = (const float*)d_in[2];
    const float* Wv = (const float*)d_in[3];
    const float* Wo = (const float*)d_in[4];
    const float* bo = (const float*)d_in[5];
    float* out = (float*)d_out;

    cudaFuncSetAttribute(qkv_h_kernel,  cudaFuncAttributeMaxDynamicSharedMemorySize, GM_SMEM);
    cudaFuncSetAttribute(out_h_kernel,  cudaFuncAttributeMaxDynamicSharedMemorySize, GM_SMEM);
    cudaFuncSetAttribute(attn_h_kernel, cudaFuncAttributeMaxDynamicSharedMemorySize, AT_SMEM);

    round_x_kernel<<<2048, 256>>>(x);
    wtrans_kernel<<<dim3(32, 32, 4), dim3(32, 8)>>>(Wq, Wk, Wv, Wo);

    dim3 gq(DD / 128, NROWS / 128, 3);
    qkv_h_kernel<<<gq, 128, GM_SMEM>>>();

    dim3 ga(SS / 64, BB * HH);
    attn_h_kernel<<<ga, 128, AT_SMEM>>>();

    dim3 go(DD / 128, NROWS / 128);
    out_h_kernel<<<go, 128, GM_SMEM>>>(bo, out);
}

// round 11
// speedup vs baseline: 1.9493x; 1.0008x over previous
#include <cuda_runtime.h>
#include <cuda_fp16.h>
#include <math.h>
#include <stdint.h>

#define BB 2
#define SS 2048
#define DD 1024
#define HH 16
#define DHD 64
#define NROWS (BB*SS)          /* 4096 */
#define ROPE_LOG2C 0.4152410118609203f   /* log2(10000)/32 */
#define SM_SCALE_LOG2E 0.1803368801111204f  /* 0.125 * log2(e) */

/* Scratch (allocation-free rule) — all fp16 */
__device__ __half g_xh[(size_t)NROWS*DD];
__device__ __half g_wq[DD*DD];     /* transposed, fp16 */
__device__ __half g_wk[DD*DD];
__device__ __half g_wv[DD*DD];
__device__ __half g_wo[DD*DD];
__device__ __half g_q[BB*HH*SS*DHD];       /* [b,h,s,d], pre-scaled by 0.125*log2e */
__device__ __half g_k[BB*HH*SS*DHD];       /* [b,h,s,d] */
__device__ __half g_v[BB*HH*SS*DHD];       /* [b,h,d,s] TRANSPOSED */
__device__ __half g_ctx[(size_t)NROWS*DD]; /* [b*s, d]  */

__device__ __forceinline__ uint32_t smem_u32_of(const void* p) {
    uint32_t a;
    asm("{ .reg .u64 t; cvta.to.shared.u64 t, %1; cvt.u32.u64 %0, t; }" : "=r"(a) : "l"(p));
    return a;
}
__device__ __forceinline__ uint32_t ldh2(const __half* p) {
    return *reinterpret_cast<const uint32_t*>(p);
}
__device__ __forceinline__ uint32_t h2pack(float a, float b) {
    __half2 h = __floats2half2_rn(a, b);
    return *reinterpret_cast<uint32_t*>(&h);
}

#define MMA_F16(c, a, b0, b1) \
    asm volatile("mma.sync.aligned.m16n8k16.row.col.f32.f16.f16.f32 " \
        "{%0,%1,%2,%3}, {%4,%5,%6,%7}, {%8,%9}, {%0,%1,%2,%3};" \
        : "+f"((c)[0]), "+f"((c)[1]), "+f"((c)[2]), "+f"((c)[3]) \
        : "r"((a)[0]), "r"((a)[1]), "r"((a)[2]), "r"((a)[3]), \
          "r"(b0), "r"(b1))

#define CP16(dst, src) \
    asm volatile("cp.async.cg.shared.global [%0], [%1], 16;" :: "r"(dst), "l"(src))
#define CPCOMMIT() asm volatile("cp.async.commit_group;" ::: "memory")
#define CPWAIT(n)  asm volatile("cp.async.wait_group %0;" :: "n"(n) : "memory")

/* ================================================================== */
/* Pre-pass 1: X -> fp16. 8 floats / thread.                          */
/* ================================================================== */
__global__ void round_x_kernel(const float* __restrict__ X)
{
    const size_t idx = (size_t)(blockIdx.x * 256 + threadIdx.x) * 8;
    float4 v0 = *reinterpret_cast<const float4*>(X + idx);
    float4 v1 = *reinterpret_cast<const float4*>(X + idx + 4);
    __half2* ph = reinterpret_cast<__half2*>(g_xh + idx);
    ph[0] = __floats2half2_rn(v0.x, v0.y);
    ph[1] = __floats2half2_rn(v0.z, v0.w);
    ph[2] = __floats2half2_rn(v1.x, v1.y);
    ph[3] = __floats2half2_rn(v1.z, v1.w);
}

/* ================================================================== */
/* Pre-pass 2: transpose + fp16-convert the 4 weight matrices.        */
/* ================================================================== */
__global__ void wtrans_kernel(const float* __restrict__ Wq,
                              const float* __restrict__ Wk,
                              const float* __restrict__ Wv,
                              const float* __restrict__ Wo)
{
    __shared__ float t[32][33];
    const int z = blockIdx.z;
    const float* src = (z == 0) ? Wq : ((z == 1) ? Wk : ((z == 2) ? Wv : Wo));
    __half* dst = (z == 0) ? g_wq : ((z == 1) ? g_wk : ((z == 2) ? g_wv : g_wo));
    const int r0 = blockIdx.y * 32, c0 = blockIdx.x * 32;
    const int tx = threadIdx.x, ty = threadIdx.y;
#pragma unroll
    for (int k = 0; k < 4; k++)
        t[ty + 8 * k][tx] = src[(size_t)(r0 + ty + 8 * k) * DD + c0 + tx];
    __syncthreads();
#pragma unroll
    for (int k = 0; k < 4; k++)
        dst[(size_t)(c0 + ty + 8 * k) * DD + r0 + tx] = __float2half_rn(t[tx][ty + 8 * k]);
}

/* ================================================================== */
/* GEMM fp16: CTA 128x128, 4 warps (64x64), BK=32, cp.async x4.       */
/* ================================================================== */
#define GM_PITCH  40                        /* halves */
#define GM_ABYTES (128*GM_PITCH*2)          /* 10240 */
#define GM_STAGE  (2*GM_ABYTES)             /* 20480 */
#define GM_SMEM   (4 * GM_STAGE)            /* 81920 */

__device__ __forceinline__ void gemm_issue_stage(
    const __half* __restrict__ A, const __half* __restrict__ Wt,
    int row0, int col0, int s, int buf, uint32_t sm)
{
    const int tid = threadIdx.x;
    const uint32_t base = sm + (uint32_t)buf * GM_STAGE;
    const int r = tid >> 2, q = tid & 3;
#pragma unroll
    for (int it = 0; it < 4; it++) {
        const int rr = r + it * 32;
        CP16(base + (uint32_t)(rr * (GM_PITCH*2) + q * 16),
             A + (size_t)(row0 + rr) * DD + s * 32 + q * 8);
        CP16(base + GM_ABYTES + (uint32_t)(rr * (GM_PITCH*2) + q * 16),
             Wt + (size_t)(col0 + rr) * DD + s * 32 + q * 8);
    }
}

__device__ __forceinline__ void gemm_h(
    const __half* __restrict__ A, const __half* __restrict__ Wt,
    int row0, int col0, char* smem, uint32_t sm, float acc[4][8][4])
{
    const int lane = threadIdx.x & 31, warp = threadIdx.x >> 5;
    const int wm = warp >> 1, wn = warp & 1;
    const int ar = lane >> 2, ac = lane & 3;

    gemm_issue_stage(A, Wt, row0, col0, 0, 0, sm); CPCOMMIT();
    gemm_issue_stage(A, Wt, row0, col0, 1, 1, sm); CPCOMMIT();
    gemm_issue_stage(A, Wt, row0, col0, 2, 2, sm); CPCOMMIT();

    for (int kt = 0; kt < 32; kt++) {
        CPWAIT(2);
        __syncthreads();
        if (kt + 3 < 32) gemm_issue_stage(A, Wt, row0, col0, kt + 3, (kt + 3) & 3, sm);
        CPCOMMIT();

        const __half* AsH = reinterpret_cast<const __half*>(smem + (size_t)(kt & 3) * GM_STAGE);
        const __half* BsH = AsH + 128 * GM_PITCH;

#pragma unroll
        for (int k16 = 0; k16 < 2; k16++) {
            const int colb = k16 * 16 + 2 * ac;
            uint32_t a[4][4], b[8][2];
#pragma unroll
            for (int i = 0; i < 4; i++) {
                const int m = wm * 64 + i * 16 + ar;
                a[i][0] = ldh2(AsH + m * GM_PITCH + colb);
                a[i][1] = ldh2(AsH + (m + 8) * GM_PITCH + colb);
                a[i][2] = ldh2(AsH + m * GM_PITCH + colb + 8);
                a[i][3] = ldh2(AsH + (m + 8) * GM_PITCH + colb + 8);
            }
#pragma unroll
            for (int j = 0; j < 8; j++) {
                const int n = wn * 64 + j * 8 + ar;
                b[j][0] = ldh2(BsH + n * GM_PITCH + colb);
                b[j][1] = ldh2(BsH + n * GM_PITCH + colb + 8);
            }
#pragma unroll
            for (int i = 0; i < 4; i++)
#pragma unroll
                for (int j = 0; j < 8; j++)
                    MMA_F16(acc[i][j], a[i], b[j][0], b[j][1]);
        }
    }
}

/* ------------------------------------------------------------------ */
__global__ void __launch_bounds__(128, 2)
qkv_h_kernel()
{
    extern __shared__ __align__(16) char smem[];
    const uint32_t sm = smem_u32_of(smem);
    const int which = blockIdx.z;
    const __half* __restrict__ Wt = (which == 0) ? g_wq : ((which == 1) ? g_wk : g_wv);
    const int row0 = blockIdx.y * 128, col0 = blockIdx.x * 128;

    float acc[4][8][4];
#pragma unroll
    for (int i = 0; i < 4; i++)
#pragma unroll
        for (int j = 0; j < 8; j++)
#pragma unroll
            for (int c = 0; c < 4; c++) acc[i][j][c] = 0.f;

    gemm_h(g_xh, Wt, row0, col0, smem, sm, acc);

    const int lane = threadIdx.x & 31, warp = threadIdx.x >> 5;
    const int wm = warp >> 1, wn = warp & 1;
    const int ar = lane >> 2, ac = lane & 3;
    const int h = (col0 >> 6) + wn;

    if (which < 2) {
        __half* __restrict__ dst = (which == 0) ? g_q : g_k;
        const float post = (which == 0) ? SM_SCALE_LOG2E : 1.0f;
        float freqs[8];
#pragma unroll
        for (int j = 0; j < 8; j++)
            freqs[j] = exp2f(-(float)(j * 4 + ac) * ROPE_LOG2C);
#pragma unroll
        for (int i = 0; i < 4; i++) {
#pragma unroll
            for (int half_ = 0; half_ < 2; half_++) {
                const int row = row0 + wm * 64 + i * 16 + ar + half_ * 8;
                const int b_ = row >> 11, s = row & (SS - 1);
                __half* drow = dst + ((size_t)(b_ * HH + h) * SS + s) * DHD;
                const float sf = (float)s;
#pragma unroll
                for (int j = 0; j < 8; j++) {
                    const int dh = j * 8 + 2 * ac;
                    const float e = acc[i][j][half_ * 2], o = acc[i][j][half_ * 2 + 1];
                    float sn, cs;
                    sincosf(sf * freqs[j], &sn, &cs);
                    *reinterpret_cast<__half2*>(&drow[dh]) =
                        __floats2half2_rn((e * cs - o * sn) * post,
                                          (e * sn + o * cs) * post);
                }
            }
        }
    } else {
        /* V: store TRANSPOSED [b,h,d,s] */
#pragma unroll
        for (int i = 0; i < 4; i++) {
#pragma unroll
            for (int half_ = 0; half_ < 2; half_++) {
                const int row = row0 + wm * 64 + i * 16 + ar + half_ * 8;
                const int b_ = row >> 11, s = row & (SS - 1);
                __half* dbase = g_v + ((size_t)(b_ * HH + h)) * DHD * SS;
#pragma unroll
                for (int j = 0; j < 8; j++) {
                    const int dh = j * 8 + 2 * ac;
                    dbase[(size_t)dh * SS + s]       = __float2half_rn(acc[i][j][half_ * 2]);
                    dbase[(size_t)(dh + 1) * SS + s] = __float2half_rn(acc[i][j][half_ * 2 + 1]);
                }
            }
        }
    }
}

/* ------------------------------------------------------------------ */
__global__ void __launch_bounds__(128, 2)
out_h_kernel(const float* __restrict__ bo, float* __restrict__ out)
{
    extern __shared__ __align__(16) char smem[];
    const uint32_t sm = smem_u32_of(smem);
    const int row0 = blockIdx.y * 128, col0 = blockIdx.x * 128;

    float acc[4][8][4];
#pragma unroll
    for (int i = 0; i < 4; i++)
#pragma unroll
        for (int j = 0; j < 8; j++)
#pragma unroll
            for (int c = 0; c < 4; c++) acc[i][j][c] = 0.f;

    gemm_h(g_ctx, g_wo, row0, col0, smem, sm, acc);

    const int lane = threadIdx.x & 31, warp = threadIdx.x >> 5;
    const int wm = warp >> 1, wn = warp & 1;
    const int ar = lane >> 2, ac = lane & 3;

#pragma unroll
    for (int i = 0; i < 4; i++) {
        const int r = row0 + wm * 64 + i * 16 + ar;
#pragma unroll
        for (int j = 0; j < 8; j++) {
            const int col = col0 + wn * 64 + j * 8 + 2 * ac;
            const float bx = bo[col], by = bo[col + 1];
            *reinterpret_cast<float2*>(&out[(size_t)r * DD + col]) =
                make_float2(acc[i][j][0] + bx, acc[i][j][1] + by);
            *reinterpret_cast<float2*>(&out[(size_t)(r + 8) * DD + col]) =
                make_float2(acc[i][j][2] + bx, acc[i][j][3] + by);
        }
    }
}

/* ================================================================== */
/* Flash attention fp16 v3: P in registers; l via ones-column MMA;    */
/* 3-buffer KV ring (1 sync/tile). q-tile 64, 4 warps x 16 q-rows.    */
/* ================================================================== */
#define AT_PITCH  72                         /* halves */
#define AT_ROWB   (AT_PITCH*2)               /* 144 B */
#define AT_TILEB  (64*AT_ROWB)               /* 9216 */
#define AT_KOFF   AT_TILEB
#define AT_VOFF   (4*AT_TILEB)
#define AT_SMEM   (7*AT_TILEB)               /* 64512 */
#define H2_ONES   0x3C003C00u

__global__ void __launch_bounds__(128, 3)
attn_h_kernel()
{
    extern __shared__ __align__(16) char smem[];
    const uint32_t sm = smem_u32_of(smem);
    const int bh = blockIdx.y;
    const int qt = gridDim.x - 1 - blockIdx.x;   /* heavy-first */
    const __half* __restrict__ Q  = g_q + (size_t)bh * SS * DHD;
    const __half* __restrict__ K  = g_k + (size_t)bh * SS * DHD;
    const __half* __restrict__ Vt = g_v + (size_t)bh * DHD * SS;  /* [d][s] */

    const int tid = threadIdx.x;
    const int lane = tid & 31, warp = tid >> 5;
    const int ar = lane >> 2, ac = lane & 3;
    const int nk = qt + 1;
    const int mrow = warp * 16;

    auto issue_kv = [&](int kt, int buf) {
#pragma unroll
        for (int it = 0; it < 4; it++) {
            const int idx = tid + it * 128;
            const int r = idx >> 3, q = idx & 7;
            CP16(sm + (uint32_t)(AT_KOFF + buf * AT_TILEB + r * AT_ROWB + q * 16),
                 K + (size_t)(kt * 64 + r) * DHD + q * 8);
            CP16(sm + (uint32_t)(AT_VOFF + buf * AT_TILEB + r * AT_ROWB + q * 16),
                 Vt + (size_t)r * SS + kt * 64 + q * 8);
        }
    };

#pragma unroll
    for (int it = 0; it < 4; it++) {
        const int idx = tid + it * 128;
        const int r = idx >> 3, q = idx & 7;
        CP16(sm + (uint32_t)(r * AT_ROWB + q * 16),
             Q + (size_t)(qt * 64 + r) * DHD + q * 8);
    }
    issue_kv(0, 0);
    CPCOMMIT();
    issue_kv(nk > 1 ? 1 : 0, 1);
    CPCOMMIT();

    CPWAIT(1);
    __syncthreads();

    /* Q fragments -> registers */
    uint32_t qf[4][4];
    {
        const __half* Qs = reinterpret_cast<const __half*>(smem);
        const int r = mrow + ar;
#pragma unroll
        for (int k16 = 0; k16 < 4; k16++) {
            const int colb = k16 * 16 + 2 * ac;
            qf[k16][0] = ldh2(Qs + r * AT_PITCH + colb);
            qf[k16][1] = ldh2(Qs + (r + 8) * AT_PITCH + colb);
            qf[k16][2] = ldh2(Qs + r * AT_PITCH + colb + 8);
            qf[k16][3] = ldh2(Qs + (r + 8) * AT_PITCH + colb + 8);
        }
    }

    float m0 = -1e30f, m1 = -1e30f;
    float o[9][4];    /* j=8 accumulates l (ones column) */
#pragma unroll
    for (int j = 0; j < 9; j++)
#pragma unroll
        for (int c = 0; c < 4; c++) o[j][c] = 0.f;

    for (int kt = 0; kt < nk; kt++) {
        CPWAIT(1);
        __syncthreads();
        if (kt + 2 < nk) issue_kv(kt + 2, (kt + 2) % 3);
        CPCOMMIT();

        const int buf = kt % 3;
        const __half* Ks = reinterpret_cast<const __half*>(smem + AT_KOFF + buf * AT_TILEB);
        const __half* Vs = reinterpret_cast<const __half*>(smem + AT_VOFF + buf * AT_TILEB);

        /* ---- S = Q K^T  (log2 domain: Q pre-scaled) ---- */
        float s[8][4];
#pragma unroll
        for (int j = 0; j < 8; j++)
#pragma unroll
            for (int c = 0; c < 4; c++) s[j][c] = 0.f;

#pragma unroll
        for (int k16 = 0; k16 < 4; k16++) {
            const int colb = k16 * 16 + 2 * ac;
#pragma unroll
            for (int j = 0; j < 8; j++) {
                const uint32_t kb0 = ldh2(Ks + (j * 8 + ar) * AT_PITCH + colb);
                const uint32_t kb1 = ldh2(Ks + (j * 8 + ar) * AT_PITCH + colb + 8);
                MMA_F16(s[j], qf[k16], kb0, kb1);
            }
        }

        /* ---- causal mask on diagonal tile ---- */
        const int r0 = mrow + ar, r1 = r0 + 8;
        if (kt == qt) {
#pragma unroll
            for (int j = 0; j < 8; j++) {
                const int c = j * 8 + 2 * ac;
                if (c     > r0) s[j][0] = -1e30f;
                if (c + 1 > r0) s[j][1] = -1e30f;
                if (c     > r1) s[j][2] = -1e30f;
                if (c + 1 > r1) s[j][3] = -1e30f;
            }
        }

        /* ---- online softmax: max + exp2 only (sum goes to tensor) ---- */
        float mx0 = -1e30f, mx1 = -1e30f;
#pragma unroll
        for (int j = 0; j < 8; j++) {
            mx0 = fmaxf(mx0, fmaxf(s[j][0], s[j][1]));
            mx1 = fmaxf(mx1, fmaxf(s[j][2], s[j][3]));
        }
        mx0 = fmaxf(mx0, __shfl_xor_sync(0xffffffffu, mx0, 1));
        mx0 = fmaxf(mx0, __shfl_xor_sync(0xffffffffu, mx0, 2));
        mx1 = fmaxf(mx1, __shfl_xor_sync(0xffffffffu, mx1, 1));
        mx1 = fmaxf(mx1, __shfl_xor_sync(0xffffffffu, mx1, 2));

        const float mn0 = fmaxf(m0, mx0), mn1 = fmaxf(m1, mx1);
        const float corr0 = exp2f(m0 - mn0), corr1 = exp2f(m1 - mn1);
        m0 = mn0; m1 = mn1;

#pragma unroll
        for (int j = 0; j < 8; j++) {
            s[j][0] = exp2f(s[j][0] - mn0);
            s[j][1] = exp2f(s[j][1] - mn0);
            s[j][2] = exp2f(s[j][2] - mn1);
            s[j][3] = exp2f(s[j][3] - mn1);
        }
#pragma unroll
        for (int j = 0; j < 9; j++) {
            o[j][0] *= corr0; o[j][1] *= corr0;
            o[j][2] *= corr1; o[j][3] *= corr1;
        }

        /* ---- O += P V, and l += P·1 via ones-column MMA ---- */
#pragma unroll
        for (int k16 = 0; k16 < 4; k16++) {
            uint32_t pa[4];
            pa[0] = h2pack(s[2 * k16][0],     s[2 * k16][1]);
            pa[1] = h2pack(s[2 * k16][2],     s[2 * k16][3]);
            pa[2] = h2pack(s[2 * k16 + 1][0], s[2 * k16 + 1][1]);
            pa[3] = h2pack(s[2 * k16 + 1][2], s[2 * k16 + 1][3]);
            const int colb = k16 * 16 + 2 * ac;
#pragma unroll
            for (int j = 0; j < 8; j++) {
                const uint32_t vb0 = ldh2(Vs + (j * 8 + ar) * AT_PITCH + colb);
                const uint32_t vb1 = ldh2(Vs + (j * 8 + ar) * AT_PITCH + colb + 8);
                MMA_F16(o[j], pa, vb0, vb1);
            }
            MMA_F16(o[8], pa, H2_ONES, H2_ONES);
        }
    }

    /* epilogue: l from ones column; normalize; write ctx fp16 [B*S, D] */
    const int b_ = bh >> 4, h = bh & (HH - 1);
    const float inv0 = 1.0f / o[8][0], inv1 = 1.0f / o[8][2];
    const int s0 = qt * 64 + mrow + ar, s1 = s0 + 8;
    __half* p0 = g_ctx + (size_t)(b_ * SS + s0) * DD + h * DHD;
    __half* p1 = g_ctx + (size_t)(b_ * SS + s1) * DD + h * DHD;
#pragma unroll
    for (int j = 0; j < 8; j++) {
        const int c = j * 8 + 2 * ac;
        *reinterpret_cast<__half2*>(&p0[c]) =
            __floats2half2_rn(o[j][0] * inv0, o[j][1] * inv0);
        *reinterpret_cast<__half2*>(&p1[c]) =
            __floats2half2_rn(o[j][2] * inv1, o[j][3] * inv1);
    }
}

/* ------------------------------------------------------------------ */
extern "C" void kernel_launch(void* const* d_in, const int* in_sizes, int n_in,
                              void* d_out, int out_size)
{
    (void)in_sizes; (void)n_in; (void)out_size;
    const float* x  = (const float*)d_in[0];
    const float* Wq = (const float*)d_in[1];
    const float* Wk = (const float*)d_in[2];
    const float* Wv = (const float*)d_in[3];
    const float* Wo = (const float*)d_in[4];
    const float* bo = (const float*)d_in[5];
    float* out = (float*)d_out;

    cudaFuncSetAttribute(qkv_h_kernel,  cudaFuncAttributeMaxDynamicSharedMemorySize, GM_SMEM);
    cudaFuncSetAttribute(out_h_kernel,  cudaFuncAttributeMaxDynamicSharedMemorySize, GM_SMEM);
    cudaFuncSetAttribute(attn_h_kernel, cudaFuncAttributeMaxDynamicSharedMemorySize, AT_SMEM);

    round_x_kernel<<<2048, 256>>>(x);
    wtrans_kernel<<<dim3(32, 32, 4), dim3(32, 8)>>>(Wq, Wk, Wv, Wo);

    dim3 gq(DD / 128, NROWS / 128, 3);
    qkv_h_kernel<<<gq, 128, GM_SMEM>>>();

    dim3 ga(SS / 64, BB * HH);
    attn_h_kernel<<<ga, 128, AT_SMEM>>>();

    dim3 go(DD / 128, NROWS / 128);
    out_h_kernel<<<go, 128, GM_SMEM>>>(bo, out);
}

// round 12
// speedup vs baseline: 2.0645x; 1.0591x over previous
#include <cuda_runtime.h>
#include <cuda_fp16.h>
#include <math.h>
#include <stdint.h>

#define BB 2
#define SS 2048
#define DD 1024
#define HH 16
#define DHD 64
#define NROWS (BB*SS)          /* 4096 */
#define ROPE_LOG2C 0.4152410118609203f   /* log2(10000)/32 */
#define SM_SCALE_LOG2E 0.1803368801111204f  /* 0.125 * log2(e) */

/* Scratch (allocation-free rule) — all fp16 */
__device__ __half g_xh[(size_t)NROWS*DD];
__device__ __half g_wq[DD*DD];     /* transposed, fp16 */
__device__ __half g_wk[DD*DD];
__device__ __half g_wv[DD*DD];
__device__ __half g_wo[DD*DD];
__device__ __half g_q[BB*HH*SS*DHD];       /* [b,h,s,d], pre-scaled by 0.125*log2e */
__device__ __half g_k[BB*HH*SS*DHD];       /* [b,h,s,d] */
__device__ __half g_v[BB*HH*SS*DHD];       /* [b,h,d,s] TRANSPOSED */
__device__ __half g_ctx[(size_t)NROWS*DD]; /* [b*s, d]  */

__device__ __forceinline__ uint32_t smem_u32_of(const void* p) {
    uint32_t a;
    asm("{ .reg .u64 t; cvta.to.shared.u64 t, %1; cvt.u32.u64 %0, t; }" : "=r"(a) : "l"(p));
    return a;
}
__device__ __forceinline__ uint32_t ldh2(const __half* p) {
    return *reinterpret_cast<const uint32_t*>(p);
}
/* pack (lo,hi) to fp16x2 and take exp2 in fp16x2 — one MUFU for two values */
__device__ __forceinline__ uint32_t ex2_h2(float lo, float hi) {
    uint32_t r;
    asm("{\n\t.reg .b32 t;\n\t"
        "cvt.rn.f16x2.f32 t, %2, %1;\n\t"
        "ex2.approx.f16x2 %0, t;\n\t}"
        : "=r"(r) : "f"(lo), "f"(hi));
    return r;
}

#define MMA_F16(c, a, b0, b1) \
    asm volatile("mma.sync.aligned.m16n8k16.row.col.f32.f16.f16.f32 " \
        "{%0,%1,%2,%3}, {%4,%5,%6,%7}, {%8,%9}, {%0,%1,%2,%3};" \
        : "+f"((c)[0]), "+f"((c)[1]), "+f"((c)[2]), "+f"((c)[3]) \
        : "r"((a)[0]), "r"((a)[1]), "r"((a)[2]), "r"((a)[3]), \
          "r"(b0), "r"(b1))

#define CP16(dst, src) \
    asm volatile("cp.async.cg.shared.global [%0], [%1], 16;" :: "r"(dst), "l"(src))
#define CPCOMMIT() asm volatile("cp.async.commit_group;" ::: "memory")
#define CPWAIT(n)  asm volatile("cp.async.wait_group %0;" :: "n"(n) : "memory")

/* ================================================================== */
/* Pre-pass 1: X -> fp16. 8 floats / thread.                          */
/* ================================================================== */
__global__ void round_x_kernel(const float* __restrict__ X)
{
    const size_t idx = (size_t)(blockIdx.x * 256 + threadIdx.x) * 8;
    float4 v0 = *reinterpret_cast<const float4*>(X + idx);
    float4 v1 = *reinterpret_cast<const float4*>(X + idx + 4);
    __half2* ph = reinterpret_cast<__half2*>(g_xh + idx);
    ph[0] = __floats2half2_rn(v0.x, v0.y);
    ph[1] = __floats2half2_rn(v0.z, v0.w);
    ph[2] = __floats2half2_rn(v1.x, v1.y);
    ph[3] = __floats2half2_rn(v1.z, v1.w);
}

/* ================================================================== */
/* Pre-pass 2: transpose + fp16-convert the 4 weight matrices.        */
/* ================================================================== */
__global__ void wtrans_kernel(const float* __restrict__ Wq,
                              const float* __restrict__ Wk,
                              const float* __restrict__ Wv,
                              const float* __restrict__ Wo)
{
    __shared__ float t[32][33];
    const int z = blockIdx.z;
    const float* src = (z == 0) ? Wq : ((z == 1) ? Wk : ((z == 2) ? Wv : Wo));
    __half* dst = (z == 0) ? g_wq : ((z == 1) ? g_wk : ((z == 2) ? g_wv : g_wo));
    const int r0 = blockIdx.y * 32, c0 = blockIdx.x * 32;
    const int tx = threadIdx.x, ty = threadIdx.y;
#pragma unroll
    for (int k = 0; k < 4; k++)
        t[ty + 8 * k][tx] = src[(size_t)(r0 + ty + 8 * k) * DD + c0 + tx];
    __syncthreads();
#pragma unroll
    for (int k = 0; k < 4; k++)
        dst[(size_t)(c0 + ty + 8 * k) * DD + r0 + tx] = __float2half_rn(t[tx][ty + 8 * k]);
}

/* ================================================================== */
/* GEMM fp16: CTA 128x128, 4 warps (64x64), BK=32, cp.async x4.       */
/* ================================================================== */
#define GM_PITCH  40                        /* halves */
#define GM_ABYTES (128*GM_PITCH*2)          /* 10240 */
#define GM_STAGE  (2*GM_ABYTES)             /* 20480 */
#define GM_SMEM   (4 * GM_STAGE)            /* 81920 */

__device__ __forceinline__ void gemm_issue_stage(
    const __half* __restrict__ A, const __half* __restrict__ Wt,
    int row0, int col0, int s, int buf, uint32_t sm)
{
    const int tid = threadIdx.x;
    const uint32_t base = sm + (uint32_t)buf * GM_STAGE;
    const int r = tid >> 2, q = tid & 3;
#pragma unroll
    for (int it = 0; it < 4; it++) {
        const int rr = r + it * 32;
        CP16(base + (uint32_t)(rr * (GM_PITCH*2) + q * 16),
             A + (size_t)(row0 + rr) * DD + s * 32 + q * 8);
        CP16(base + GM_ABYTES + (uint32_t)(rr * (GM_PITCH*2) + q * 16),
             Wt + (size_t)(col0 + rr) * DD + s * 32 + q * 8);
    }
}

__device__ __forceinline__ void gemm_h(
    const __half* __restrict__ A, const __half* __restrict__ Wt,
    int row0, int col0, char* smem, uint32_t sm, float acc[4][8][4])
{
    const int lane = threadIdx.x & 31, warp = threadIdx.x >> 5;
    const int wm = warp >> 1, wn = warp & 1;
    const int ar = lane >> 2, ac = lane & 3;

    gemm_issue_stage(A, Wt, row0, col0, 0, 0, sm); CPCOMMIT();
    gemm_issue_stage(A, Wt, row0, col0, 1, 1, sm); CPCOMMIT();
    gemm_issue_stage(A, Wt, row0, col0, 2, 2, sm); CPCOMMIT();

    for (int kt = 0; kt < 32; kt++) {
        CPWAIT(2);
        __syncthreads();
        if (kt + 3 < 32) gemm_issue_stage(A, Wt, row0, col0, kt + 3, (kt + 3) & 3, sm);
        CPCOMMIT();

        const __half* AsH = reinterpret_cast<const __half*>(smem + (size_t)(kt & 3) * GM_STAGE);
        const __half* BsH = AsH + 128 * GM_PITCH;

#pragma unroll
        for (int k16 = 0; k16 < 2; k16++) {
            const int colb = k16 * 16 + 2 * ac;
            uint32_t a[4][4], b[8][2];
#pragma unroll
            for (int i = 0; i < 4; i++) {
                const int m = wm * 64 + i * 16 + ar;
                a[i][0] = ldh2(AsH + m * GM_PITCH + colb);
                a[i][1] = ldh2(AsH + (m + 8) * GM_PITCH + colb);
                a[i][2] = ldh2(AsH + m * GM_PITCH + colb + 8);
                a[i][3] = ldh2(AsH + (m + 8) * GM_PITCH + colb + 8);
            }
#pragma unroll
            for (int j = 0; j < 8; j++) {
                const int n = wn * 64 + j * 8 + ar;
                b[j][0] = ldh2(BsH + n * GM_PITCH + colb);
                b[j][1] = ldh2(BsH + n * GM_PITCH + colb + 8);
            }
#pragma unroll
            for (int i = 0; i < 4; i++)
#pragma unroll
                for (int j = 0; j < 8; j++)
                    MMA_F16(acc[i][j], a[i], b[j][0], b[j][1]);
        }
    }
}

/* ------------------------------------------------------------------ */
__global__ void __launch_bounds__(128, 2)
qkv_h_kernel()
{
    extern __shared__ __align__(16) char smem[];
    const uint32_t sm = smem_u32_of(smem);
    const int which = blockIdx.z;
    const __half* __restrict__ Wt = (which == 0) ? g_wq : ((which == 1) ? g_wk : g_wv);
    const int row0 = blockIdx.y * 128, col0 = blockIdx.x * 128;

    float acc[4][8][4];
#pragma unroll
    for (int i = 0; i < 4; i++)
#pragma unroll
        for (int j = 0; j < 8; j++)
#pragma unroll
            for (int c = 0; c < 4; c++) acc[i][j][c] = 0.f;

    gemm_h(g_xh, Wt, row0, col0, smem, sm, acc);

    const int lane = threadIdx.x & 31, warp = threadIdx.x >> 5;
    const int wm = warp >> 1, wn = warp & 1;
    const int ar = lane >> 2, ac = lane & 3;
    const int h = (col0 >> 6) + wn;

    if (which < 2) {
        __half* __restrict__ dst = (which == 0) ? g_q : g_k;
        const float post = (which == 0) ? SM_SCALE_LOG2E : 1.0f;
        /* this thread's 8 rows are base + 8t (same batch, consecutive s) */
        const int rowb = row0 + wm * 64 + ar;
        const int b_ = rowb >> 11, sbase = rowb & (SS - 1);
        __half* dhead = dst + ((size_t)(b_ * HH + h) * SS) * DHD;
#pragma unroll
        for (int j = 0; j < 8; j++) {
            const float freq = exp2f(-(float)(j * 4 + ac) * ROPE_LOG2C);
            const int dh = j * 8 + 2 * ac;
            float sn, cs, sd, cd;
            sincosf((float)sbase * freq, &sn, &cs);
            sincosf(8.0f * freq, &sd, &cd);
#pragma unroll
            for (int t = 0; t < 8; t++) {
                const int i = t >> 1, half_ = t & 1;
                const float e = acc[i][j][half_ * 2], o = acc[i][j][half_ * 2 + 1];
                __half* drow = dhead + (size_t)(sbase + 8 * t) * DHD;
                *reinterpret_cast<__half2*>(&drow[dh]) =
                    __floats2half2_rn((e * cs - o * sn) * post,
                                      (e * sn + o * cs) * post);
                const float csn = cs * cd - sn * sd;
                sn = sn * cd + cs * sd;
                cs = csn;
            }
        }
    } else {
        /* V: store TRANSPOSED [b,h,d,s] */
#pragma unroll
        for (int i = 0; i < 4; i++) {
#pragma unroll
            for (int half_ = 0; half_ < 2; half_++) {
                const int row = row0 + wm * 64 + i * 16 + ar + half_ * 8;
                const int b_ = row >> 11, s = row & (SS - 1);
                __half* dbase = g_v + ((size_t)(b_ * HH + h)) * DHD * SS;
#pragma unroll
                for (int j = 0; j < 8; j++) {
                    const int dh = j * 8 + 2 * ac;
                    dbase[(size_t)dh * SS + s]       = __float2half_rn(acc[i][j][half_ * 2]);
                    dbase[(size_t)(dh + 1) * SS + s] = __float2half_rn(acc[i][j][half_ * 2 + 1]);
                }
            }
        }
    }
}

/* ------------------------------------------------------------------ */
__global__ void __launch_bounds__(128, 2)
out_h_kernel(const float* __restrict__ bo, float* __restrict__ out)
{
    extern __shared__ __align__(16) char smem[];
    const uint32_t sm = smem_u32_of(smem);
    const int row0 = blockIdx.y * 128, col0 = blockIdx.x * 128;

    float acc[4][8][4];
#pragma unroll
    for (int i = 0; i < 4; i++)
#pragma unroll
        for (int j = 0; j < 8; j++)
#pragma unroll
            for (int c = 0; c < 4; c++) acc[i][j][c] = 0.f;

    gemm_h(g_ctx, g_wo, row0, col0, smem, sm, acc);

    const int lane = threadIdx.x & 31, warp = threadIdx.x >> 5;
    const int wm = warp >> 1, wn = warp & 1;
    const int ar = lane >> 2, ac = lane & 3;

#pragma unroll
    for (int i = 0; i < 4; i++) {
        const int r = row0 + wm * 64 + i * 16 + ar;
#pragma unroll
        for (int j = 0; j < 8; j++) {
            const int col = col0 + wn * 64 + j * 8 + 2 * ac;
            const float bx = bo[col], by = bo[col + 1];
            *reinterpret_cast<float2*>(&out[(size_t)r * DD + col]) =
                make_float2(acc[i][j][0] + bx, acc[i][j][1] + by);
            *reinterpret_cast<float2*>(&out[(size_t)(r + 8) * DD + col]) =
                make_float2(acc[i][j][2] + bx, acc[i][j][3] + by);
        }
    }
}

/* ================================================================== */
/* Flash attention fp16 v4: P via fused f16x2 ex2 (one MUFU / pair);  */
/* l via ones-column MMA; 3-buffer KV ring (1 sync/tile).             */
/* ================================================================== */
#define AT_PITCH  72                         /* halves */
#define AT_ROWB   (AT_PITCH*2)               /* 144 B */
#define AT_TILEB  (64*AT_ROWB)               /* 9216 */
#define AT_KOFF   AT_TILEB
#define AT_VOFF   (4*AT_TILEB)
#define AT_SMEM   (7*AT_TILEB)               /* 64512 */
#define H2_ONES   0x3C003C00u

__global__ void __launch_bounds__(128, 3)
attn_h_kernel()
{
    extern __shared__ __align__(16) char smem[];
    const uint32_t sm = smem_u32_of(smem);
    const int bh = blockIdx.y;
    const int qt = gridDim.x - 1 - blockIdx.x;   /* heavy-first */
    const __half* __restrict__ Q  = g_q + (size_t)bh * SS * DHD;
    const __half* __restrict__ K  = g_k + (size_t)bh * SS * DHD;
    const __half* __restrict__ Vt = g_v + (size_t)bh * DHD * SS;  /* [d][s] */

    const int tid = threadIdx.x;
    const int lane = tid & 31, warp = tid >> 5;
    const int ar = lane >> 2, ac = lane & 3;
    const int nk = qt + 1;
    const int mrow = warp * 16;

    auto issue_kv = [&](int kt, int buf) {
#pragma unroll
        for (int it = 0; it < 4; it++) {
            const int idx = tid + it * 128;
            const int r = idx >> 3, q = idx & 7;
            CP16(sm + (uint32_t)(AT_KOFF + buf * AT_TILEB + r * AT_ROWB + q * 16),
                 K + (size_t)(kt * 64 + r) * DHD + q * 8);
            CP16(sm + (uint32_t)(AT_VOFF + buf * AT_TILEB + r * AT_ROWB + q * 16),
                 Vt + (size_t)r * SS + kt * 64 + q * 8);
        }
    };

#pragma unroll
    for (int it = 0; it < 4; it++) {
        const int idx = tid + it * 128;
        const int r = idx >> 3, q = idx & 7;
        CP16(sm + (uint32_t)(r * AT_ROWB + q * 16),
             Q + (size_t)(qt * 64 + r) * DHD + q * 8);
    }
    issue_kv(0, 0);
    CPCOMMIT();
    issue_kv(nk > 1 ? 1 : 0, 1);
    CPCOMMIT();

    CPWAIT(1);
    __syncthreads();

    /* Q fragments -> registers */
    uint32_t qf[4][4];
    {
        const __half* Qs = reinterpret_cast<const __half*>(smem);
        const int r = mrow + ar;
#pragma unroll
        for (int k16 = 0; k16 < 4; k16++) {
            const int colb = k16 * 16 + 2 * ac;
            qf[k16][0] = ldh2(Qs + r * AT_PITCH + colb);
            qf[k16][1] = ldh2(Qs + (r + 8) * AT_PITCH + colb);
            qf[k16][2] = ldh2(Qs + r * AT_PITCH + colb + 8);
            qf[k16][3] = ldh2(Qs + (r + 8) * AT_PITCH + colb + 8);
        }
    }

    float m0 = -1e30f, m1 = -1e30f;
    float o[9][4];    /* j=8 accumulates l (ones column) */
#pragma unroll
    for (int j = 0; j < 9; j++)
#pragma unroll
        for (int c = 0; c < 4; c++) o[j][c] = 0.f;

    for (int kt = 0; kt < nk; kt++) {
        CPWAIT(1);
        __syncthreads();
        if (kt + 2 < nk) issue_kv(kt + 2, (kt + 2) % 3);
        CPCOMMIT();

        const int buf = kt % 3;
        const __half* Ks = reinterpret_cast<const __half*>(smem + AT_KOFF + buf * AT_TILEB);
        const __half* Vs = reinterpret_cast<const __half*>(smem + AT_VOFF + buf * AT_TILEB);

        /* ---- S = Q K^T  (log2 domain: Q pre-scaled) ---- */
        float s[8][4];
#pragma unroll
        for (int j = 0; j < 8; j++)
#pragma unroll
            for (int c = 0; c < 4; c++) s[j][c] = 0.f;

#pragma unroll
        for (int k16 = 0; k16 < 4; k16++) {
            const int colb = k16 * 16 + 2 * ac;
#pragma unroll
            for (int j = 0; j < 8; j++) {
                const uint32_t kb0 = ldh2(Ks + (j * 8 + ar) * AT_PITCH + colb);
                const uint32_t kb1 = ldh2(Ks + (j * 8 + ar) * AT_PITCH + colb + 8);
                MMA_F16(s[j], qf[k16], kb0, kb1);
            }
        }

        /* ---- causal mask on diagonal tile ---- */
        const int r0 = mrow + ar, r1 = r0 + 8;
        if (kt == qt) {
#pragma unroll
            for (int j = 0; j < 8; j++) {
                const int c = j * 8 + 2 * ac;
                if (c     > r0) s[j][0] = -1e30f;
                if (c + 1 > r0) s[j][1] = -1e30f;
                if (c     > r1) s[j][2] = -1e30f;
                if (c + 1 > r1) s[j][3] = -1e30f;
            }
        }

        /* ---- online softmax: max + fused f16x2 exp2 ---- */
        float mx0 = -1e30f, mx1 = -1e30f;
#pragma unroll
        for (int j = 0; j < 8; j++) {
            mx0 = fmaxf(mx0, fmaxf(s[j][0], s[j][1]));
            mx1 = fmaxf(mx1, fmaxf(s[j][2], s[j][3]));
        }
        mx0 = fmaxf(mx0, __shfl_xor_sync(0xffffffffu, mx0, 1));
        mx0 = fmaxf(mx0, __shfl_xor_sync(0xffffffffu, mx0, 2));
        mx1 = fmaxf(mx1, __shfl_xor_sync(0xffffffffu, mx1, 1));
        mx1 = fmaxf(mx1, __shfl_xor_sync(0xffffffffu, mx1, 2));

        const float mn0 = fmaxf(m0, mx0), mn1 = fmaxf(m1, mx1);
        const float corr0 = exp2f(m0 - mn0), corr1 = exp2f(m1 - mn1);
        m0 = mn0; m1 = mn1;

        /* P fragments directly as packed fp16 pairs */
        uint32_t pe[8][2];
#pragma unroll
        for (int j = 0; j < 8; j++) {
            pe[j][0] = ex2_h2(s[j][0] - mn0, s[j][1] - mn0);
            pe[j][1] = ex2_h2(s[j][2] - mn1, s[j][3] - mn1);
        }
#pragma unroll
        for (int j = 0; j < 9; j++) {
            o[j][0] *= corr0; o[j][1] *= corr0;
            o[j][2] *= corr1; o[j][3] *= corr1;
        }

        /* ---- O += P V, and l += P·1 via ones-column MMA ---- */
#pragma unroll
        for (int k16 = 0; k16 < 4; k16++) {
            uint32_t pa[4];
            pa[0] = pe[2 * k16][0];
            pa[1] = pe[2 * k16][1];
            pa[2] = pe[2 * k16 + 1][0];
            pa[3] = pe[2 * k16 + 1][1];
            const int colb = k16 * 16 + 2 * ac;
#pragma unroll
            for (int j = 0; j < 8; j++) {
                const uint32_t vb0 = ldh2(Vs + (j * 8 + ar) * AT_PITCH + colb);
                const uint32_t vb1 = ldh2(Vs + (j * 8 + ar) * AT_PITCH + colb + 8);
                MMA_F16(o[j], pa, vb0, vb1);
            }
            MMA_F16(o[8], pa, H2_ONES, H2_ONES);
        }
    }

    /* epilogue: l from ones column; normalize; write ctx fp16 [B*S, D] */
    const int b_ = bh >> 4, h = bh & (HH - 1);
    const float inv0 = 1.0f / o[8][0], inv1 = 1.0f / o[8][2];
    const int s0 = qt * 64 + mrow + ar, s1 = s0 + 8;
    __half* p0 = g_ctx + (size_t)(b_ * SS + s0) * DD + h * DHD;
    __half* p1 = g_ctx + (size_t)(b_ * SS + s1) * DD + h * DHD;
#pragma unroll
    for (int j = 0; j < 8; j++) {
        const int c = j * 8 + 2 * ac;
        *reinterpret_cast<__half2*>(&p0[c]) =
            __floats2half2_rn(o[j][0] * inv0, o[j][1] * inv0);
        *reinterpret_cast<__half2*>(&p1[c]) =
            __floats2half2_rn(o[j][2] * inv1, o[j][3] * inv1);
    }
}

/* ------------------------------------------------------------------ */
extern "C" void kernel_launch(void* const* d_in, const int* in_sizes, int n_in,
                              void* d_out, int out_size)
{
    (void)in_sizes; (void)n_in; (void)out_size;
    const float* x  = (const float*)d_in[0];
    const float* Wq = (const float*)d_in[1];
    const float* Wk = (const float*)d_in[2];
    const float* Wv = (const float*)d_in[3];
    const float* Wo = (const float*)d_in[4];
    const float* bo = (const float*)d_in[5];
    float* out = (float*)d_out;

    cudaFuncSetAttribute(qkv_h_kernel,  cudaFuncAttributeMaxDynamicSharedMemorySize, GM_SMEM);
    cudaFuncSetAttribute(out_h_kernel,  cudaFuncAttributeMaxDynamicSharedMemorySize, GM_SMEM);
    cudaFuncSetAttribute(attn_h_kernel, cudaFuncAttributeMaxDynamicSharedMemorySize, AT_SMEM);

    round_x_kernel<<<2048, 256>>>(x);
    wtrans_kernel<<<dim3(32, 32, 4), dim3(32, 8)>>>(Wq, Wk, Wv, Wo);

    dim3 gq(DD / 128, NROWS / 128, 3);
    qkv_h_kernel<<<gq, 128, GM_SMEM>>>();

    dim3 ga(SS / 64, BB * HH);
    attn_h_kernel<<<ga, 128, AT_SMEM>>>();

    dim3 go(DD / 128, NROWS / 128);
    out_h_kernel<<<go, 128, GM_SMEM>>>(bo, out);
}

// round 13
// speedup vs baseline: 2.1191x; 1.0265x over previous
#include <cuda_runtime.h>
#include <cuda_fp16.h>
#include <math.h>
#include <stdint.h>

#define BB 2
#define SS 2048
#define DD 1024
#define HH 16
#define DHD 64
#define NROWS (BB*SS)          /* 4096 */
#define ROPE_LOG2C 0.4152410118609203f   /* log2(10000)/32 */
#define SM_SCALE_LOG2E 0.1803368801111204f  /* 0.125 * log2(e) */

/* Scratch (allocation-free rule) — all fp16 */
__device__ __half g_xh[(size_t)NROWS*DD];
__device__ __half g_wq[DD*DD];     /* transposed, fp16 */
__device__ __half g_wk[DD*DD];
__device__ __half g_wv[DD*DD];
__device__ __half g_wo[DD*DD];
__device__ __half g_q[BB*HH*SS*DHD];       /* [b,h,s,d], pre-scaled by 0.125*log2e */
__device__ __half g_k[BB*HH*SS*DHD];       /* [b,h,s,d] */
__device__ __half g_v[BB*HH*SS*DHD];       /* [b,h,d,s] TRANSPOSED */
__device__ __half g_ctx[(size_t)NROWS*DD]; /* [b*s, d]  */

__device__ __forceinline__ uint32_t smem_u32_of(const void* p) {
    uint32_t a;
    asm("{ .reg .u64 t; cvta.to.shared.u64 t, %1; cvt.u32.u64 %0, t; }" : "=r"(a) : "l"(p));
    return a;
}
__device__ __forceinline__ uint32_t ldh2(const __half* p) {
    return *reinterpret_cast<const uint32_t*>(p);
}
/* pack (lo,hi) to fp16x2 and take exp2 in fp16x2 — one MUFU for two values */
__device__ __forceinline__ uint32_t ex2_h2(float lo, float hi) {
    uint32_t r;
    asm("{\n\t.reg .b32 t;\n\t"
        "cvt.rn.f16x2.f32 t, %2, %1;\n\t"
        "ex2.approx.f16x2 %0, t;\n\t}"
        : "=r"(r) : "f"(lo), "f"(hi));
    return r;
}

#define MMA_F16(c, a, b0, b1) \
    asm volatile("mma.sync.aligned.m16n8k16.row.col.f32.f16.f16.f32 " \
        "{%0,%1,%2,%3}, {%4,%5,%6,%7}, {%8,%9}, {%0,%1,%2,%3};" \
        : "+f"((c)[0]), "+f"((c)[1]), "+f"((c)[2]), "+f"((c)[3]) \
        : "r"((a)[0]), "r"((a)[1]), "r"((a)[2]), "r"((a)[3]), \
          "r"(b0), "r"(b1))

#define LDSM4(d0, d1, d2, d3, addr) \
    asm volatile("ldmatrix.sync.aligned.m8n8.x4.shared.b16 {%0,%1,%2,%3}, [%4];" \
        : "=r"(d0), "=r"(d1), "=r"(d2), "=r"(d3) : "r"(addr))

#define CP16(dst, src) \
    asm volatile("cp.async.cg.shared.global [%0], [%1], 16;" :: "r"(dst), "l"(src))
#define CPCOMMIT() asm volatile("cp.async.commit_group;" ::: "memory")
#define CPWAIT(n)  asm volatile("cp.async.wait_group %0;" :: "n"(n) : "memory")

/* ================================================================== */
/* Pre-pass 1: X -> fp16. 8 floats / thread.                          */
/* ================================================================== */
__global__ void round_x_kernel(const float* __restrict__ X)
{
    const size_t idx = (size_t)(blockIdx.x * 256 + threadIdx.x) * 8;
    float4 v0 = *reinterpret_cast<const float4*>(X + idx);
    float4 v1 = *reinterpret_cast<const float4*>(X + idx + 4);
    __half2* ph = reinterpret_cast<__half2*>(g_xh + idx);
    ph[0] = __floats2half2_rn(v0.x, v0.y);
    ph[1] = __floats2half2_rn(v0.z, v0.w);
    ph[2] = __floats2half2_rn(v1.x, v1.y);
    ph[3] = __floats2half2_rn(v1.z, v1.w);
}

/* ================================================================== */
/* Pre-pass 2: transpose + fp16-convert the 4 weight matrices.        */
/* ================================================================== */
__global__ void wtrans_kernel(const float* __restrict__ Wq,
                              const float* __restrict__ Wk,
                              const float* __restrict__ Wv,
                              const float* __restrict__ Wo)
{
    __shared__ float t[32][33];
    const int z = blockIdx.z;
    const float* src = (z == 0) ? Wq : ((z == 1) ? Wk : ((z == 2) ? Wv : Wo));
    __half* dst = (z == 0) ? g_wq : ((z == 1) ? g_wk : ((z == 2) ? g_wv : g_wo));
    const int r0 = blockIdx.y * 32, c0 = blockIdx.x * 32;
    const int tx = threadIdx.x, ty = threadIdx.y;
#pragma unroll
    for (int k = 0; k < 4; k++)
        t[ty + 8 * k][tx] = src[(size_t)(r0 + ty + 8 * k) * DD + c0 + tx];
    __syncthreads();
#pragma unroll
    for (int k = 0; k < 4; k++)
        dst[(size_t)(c0 + ty + 8 * k) * DD + r0 + tx] = __float2half_rn(t[tx][ty + 8 * k]);
}

/* ================================================================== */
/* GEMM fp16: CTA 128x128, 4 warps (64x64), BK=32, cp.async x4.       */
/* ================================================================== */
#define GM_PITCH  40                        /* halves */
#define GM_ABYTES (128*GM_PITCH*2)          /* 10240 */
#define GM_STAGE  (2*GM_ABYTES)             /* 20480 */
#define GM_SMEM   (4 * GM_STAGE)            /* 81920 */

__device__ __forceinline__ void gemm_issue_stage(
    const __half* __restrict__ A, const __half* __restrict__ Wt,
    int row0, int col0, int s, int buf, uint32_t sm)
{
    const int tid = threadIdx.x;
    const uint32_t base = sm + (uint32_t)buf * GM_STAGE;
    const int r = tid >> 2, q = tid & 3;
#pragma unroll
    for (int it = 0; it < 4; it++) {
        const int rr = r + it * 32;
        CP16(base + (uint32_t)(rr * (GM_PITCH*2) + q * 16),
             A + (size_t)(row0 + rr) * DD + s * 32 + q * 8);
        CP16(base + GM_ABYTES + (uint32_t)(rr * (GM_PITCH*2) + q * 16),
             Wt + (size_t)(col0 + rr) * DD + s * 32 + q * 8);
    }
}

__device__ __forceinline__ void gemm_h(
    const __half* __restrict__ A, const __half* __restrict__ Wt,
    int row0, int col0, char* smem, uint32_t sm, float acc[4][8][4])
{
    const int lane = threadIdx.x & 31, warp = threadIdx.x >> 5;
    const int wm = warp >> 1, wn = warp & 1;
    const int ar = lane >> 2, ac = lane & 3;

    gemm_issue_stage(A, Wt, row0, col0, 0, 0, sm); CPCOMMIT();
    gemm_issue_stage(A, Wt, row0, col0, 1, 1, sm); CPCOMMIT();
    gemm_issue_stage(A, Wt, row0, col0, 2, 2, sm); CPCOMMIT();

    for (int kt = 0; kt < 32; kt++) {
        CPWAIT(2);
        __syncthreads();
        if (kt + 3 < 32) gemm_issue_stage(A, Wt, row0, col0, kt + 3, (kt + 3) & 3, sm);
        CPCOMMIT();

        const __half* AsH = reinterpret_cast<const __half*>(smem + (size_t)(kt & 3) * GM_STAGE);
        const __half* BsH = AsH + 128 * GM_PITCH;

#pragma unroll
        for (int k16 = 0; k16 < 2; k16++) {
            const int colb = k16 * 16 + 2 * ac;
            uint32_t a[4][4], b[8][2];
#pragma unroll
            for (int i = 0; i < 4; i++) {
                const int m = wm * 64 + i * 16 + ar;
                a[i][0] = ldh2(AsH + m * GM_PITCH + colb);
                a[i][1] = ldh2(AsH + (m + 8) * GM_PITCH + colb);
                a[i][2] = ldh2(AsH + m * GM_PITCH + colb + 8);
                a[i][3] = ldh2(AsH + (m + 8) * GM_PITCH + colb + 8);
            }
#pragma unroll
            for (int j = 0; j < 8; j++) {
                const int n = wn * 64 + j * 8 + ar;
                b[j][0] = ldh2(BsH + n * GM_PITCH + colb);
                b[j][1] = ldh2(BsH + n * GM_PITCH + colb + 8);
            }
#pragma unroll
            for (int i = 0; i < 4; i++)
#pragma unroll
                for (int j = 0; j < 8; j++)
                    MMA_F16(acc[i][j], a[i], b[j][0], b[j][1]);
        }
    }
}

/* ------------------------------------------------------------------ */
__global__ void __launch_bounds__(128, 2)
qkv_h_kernel()
{
    extern __shared__ __align__(16) char smem[];
    const uint32_t sm = smem_u32_of(smem);
    const int which = blockIdx.z;
    const __half* __restrict__ Wt = (which == 0) ? g_wq : ((which == 1) ? g_wk : g_wv);
    const int row0 = blockIdx.y * 128, col0 = blockIdx.x * 128;

    float acc[4][8][4];
#pragma unroll
    for (int i = 0; i < 4; i++)
#pragma unroll
        for (int j = 0; j < 8; j++)
#pragma unroll
            for (int c = 0; c < 4; c++) acc[i][j][c] = 0.f;

    gemm_h(g_xh, Wt, row0, col0, smem, sm, acc);

    const int lane = threadIdx.x & 31, warp = threadIdx.x >> 5;
    const int wm = warp >> 1, wn = warp & 1;
    const int ar = lane >> 2, ac = lane & 3;
    const int h = (col0 >> 6) + wn;

    if (which < 2) {
        __half* __restrict__ dst = (which == 0) ? g_q : g_k;
        const float post = (which == 0) ? SM_SCALE_LOG2E : 1.0f;
        /* this thread's 8 rows are base + 8t (same batch, consecutive s) */
        const int rowb = row0 + wm * 64 + ar;
        const int b_ = rowb >> 11, sbase = rowb & (SS - 1);
        __half* dhead = dst + ((size_t)(b_ * HH + h) * SS) * DHD;
#pragma unroll
        for (int j = 0; j < 8; j++) {
            const float freq = exp2f(-(float)(j * 4 + ac) * ROPE_LOG2C);
            const int dh = j * 8 + 2 * ac;
            float sn, cs, sd, cd;
            sincosf((float)sbase * freq, &sn, &cs);
            sincosf(8.0f * freq, &sd, &cd);
#pragma unroll
            for (int t = 0; t < 8; t++) {
                const int i = t >> 1, half_ = t & 1;
                const float e = acc[i][j][half_ * 2], o = acc[i][j][half_ * 2 + 1];
                __half* drow = dhead + (size_t)(sbase + 8 * t) * DHD;
                *reinterpret_cast<__half2*>(&drow[dh]) =
                    __floats2half2_rn((e * cs - o * sn) * post,
                                      (e * sn + o * cs) * post);
                const float csn = cs * cd - sn * sd;
                sn = sn * cd + cs * sd;
                cs = csn;
            }
        }
    } else {
        /* V: store TRANSPOSED [b,h,d,s] */
#pragma unroll
        for (int i = 0; i < 4; i++) {
#pragma unroll
            for (int half_ = 0; half_ < 2; half_++) {
                const int row = row0 + wm * 64 + i * 16 + ar + half_ * 8;
                const int b_ = row >> 11, s = row & (SS - 1);
                __half* dbase = g_v + ((size_t)(b_ * HH + h)) * DHD * SS;
#pragma unroll
                for (int j = 0; j < 8; j++) {
                    const int dh = j * 8 + 2 * ac;
                    dbase[(size_t)dh * SS + s]       = __float2half_rn(acc[i][j][half_ * 2]);
                    dbase[(size_t)(dh + 1) * SS + s] = __float2half_rn(acc[i][j][half_ * 2 + 1]);
                }
            }
        }
    }
}

/* ------------------------------------------------------------------ */
__global__ void __launch_bounds__(128, 2)
out_h_kernel(const float* __restrict__ bo, float* __restrict__ out)
{
    extern __shared__ __align__(16) char smem[];
    const uint32_t sm = smem_u32_of(smem);
    const int row0 = blockIdx.y * 128, col0 = blockIdx.x * 128;

    float acc[4][8][4];
#pragma unroll
    for (int i = 0; i < 4; i++)
#pragma unroll
        for (int j = 0; j < 8; j++)
#pragma unroll
            for (int c = 0; c < 4; c++) acc[i][j][c] = 0.f;

    gemm_h(g_ctx, g_wo, row0, col0, smem, sm, acc);

    const int lane = threadIdx.x & 31, warp = threadIdx.x >> 5;
    const int wm = warp >> 1, wn = warp & 1;
    const int ar = lane >> 2, ac = lane & 3;

#pragma unroll
    for (int i = 0; i < 4; i++) {
        const int r = row0 + wm * 64 + i * 16 + ar;
#pragma unroll
        for (int j = 0; j < 8; j++) {
            const int col = col0 + wn * 64 + j * 8 + 2 * ac;
            const float bx = bo[col], by = bo[col + 1];
            *reinterpret_cast<float2*>(&out[(size_t)r * DD + col]) =
                make_float2(acc[i][j][0] + bx, acc[i][j][1] + by);
            *reinterpret_cast<float2*>(&out[(size_t)(r + 8) * DD + col]) =
                make_float2(acc[i][j][2] + bx, acc[i][j][3] + by);
        }
    }
}

/* ================================================================== */
/* Flash attention fp16 v5: K/V fragments via ldmatrix.x4;            */
/* P via fused f16x2 ex2; l via ones-column MMA; 3-buffer KV ring.    */
/* ================================================================== */
#define AT_PITCH  72                         /* halves */
#define AT_ROWB   (AT_PITCH*2)               /* 144 B */
#define AT_TILEB  (64*AT_ROWB)               /* 9216 */
#define AT_KOFF   AT_TILEB
#define AT_VOFF   (4*AT_TILEB)
#define AT_SMEM   (7*AT_TILEB)               /* 64512 */
#define H2_ONES   0x3C003C00u

__global__ void __launch_bounds__(128, 3)
attn_h_kernel()
{
    extern __shared__ __align__(16) char smem[];
    const uint32_t sm = smem_u32_of(smem);
    const int bh = blockIdx.y;
    const int qt = gridDim.x - 1 - blockIdx.x;   /* heavy-first */
    const __half* __restrict__ Q  = g_q + (size_t)bh * SS * DHD;
    const __half* __restrict__ K  = g_k + (size_t)bh * SS * DHD;
    const __half* __restrict__ Vt = g_v + (size_t)bh * DHD * SS;  /* [d][s] */

    const int tid = threadIdx.x;
    const int lane = tid & 31, warp = tid >> 5;
    const int ar = lane >> 2, ac = lane & 3;
    const int nk = qt + 1;
    const int mrow = warp * 16;

    /* ldmatrix per-lane row address component (bytes, tile-relative):
       lanes 0-15 -> j-pair member 0, lanes 16-31 -> member 1;
       within each 16: lanes 0-7 k-offset 0, lanes 8-15 k-offset +8 halves. */
    const uint32_t lnrow = (uint32_t)(lane & 7);
    const uint32_t jsel  = (uint32_t)(lane >> 4);          /* 0 or 1 */
    const uint32_t ksel  = (uint32_t)((lane >> 3) & 1) * 16;  /* bytes */
    uint32_t lm_base[4];
#pragma unroll
    for (int t = 0; t < 4; t++)
        lm_base[t] = ((2 * t + jsel) * 8 + lnrow) * AT_ROWB + ksel;

    auto issue_kv = [&](int kt, int buf) {
#pragma unroll
        for (int it = 0; it < 4; it++) {
            const int idx = tid + it * 128;
            const int r = idx >> 3, q = idx & 7;
            CP16(sm + (uint32_t)(AT_KOFF + buf * AT_TILEB + r * AT_ROWB + q * 16),
                 K + (size_t)(kt * 64 + r) * DHD + q * 8);
            CP16(sm + (uint32_t)(AT_VOFF + buf * AT_TILEB + r * AT_ROWB + q * 16),
                 Vt + (size_t)r * SS + kt * 64 + q * 8);
        }
    };

#pragma unroll
    for (int it = 0; it < 4; it++) {
        const int idx = tid + it * 128;
        const int r = idx >> 3, q = idx & 7;
        CP16(sm + (uint32_t)(r * AT_ROWB + q * 16),
             Q + (size_t)(qt * 64 + r) * DHD + q * 8);
    }
    issue_kv(0, 0);
    CPCOMMIT();
    issue_kv(nk > 1 ? 1 : 0, 1);
    CPCOMMIT();

    CPWAIT(1);
    __syncthreads();

    /* Q fragments -> registers */
    uint32_t qf[4][4];
    {
        const __half* Qs = reinterpret_cast<const __half*>(smem);
        const int r = mrow + ar;
#pragma unroll
        for (int k16 = 0; k16 < 4; k16++) {
            const int colb = k16 * 16 + 2 * ac;
            qf[k16][0] = ldh2(Qs + r * AT_PITCH + colb);
            qf[k16][1] = ldh2(Qs + (r + 8) * AT_PITCH + colb);
            qf[k16][2] = ldh2(Qs + r * AT_PITCH + colb + 8);
            qf[k16][3] = ldh2(Qs + (r + 8) * AT_PITCH + colb + 8);
        }
    }

    float m0 = -1e30f, m1 = -1e30f;
    float o[9][4];    /* j=8 accumulates l (ones column) */
#pragma unroll
    for (int j = 0; j < 9; j++)
#pragma unroll
        for (int c = 0; c < 4; c++) o[j][c] = 0.f;

    for (int kt = 0; kt < nk; kt++) {
        CPWAIT(1);
        __syncthreads();
        if (kt + 2 < nk) issue_kv(kt + 2, (kt + 2) % 3);
        CPCOMMIT();

        const int buf = kt % 3;
        const uint32_t kbase = sm + AT_KOFF + buf * AT_TILEB;
        const uint32_t vbase = sm + AT_VOFF + buf * AT_TILEB;

        /* ---- S = Q K^T  (log2 domain: Q pre-scaled) ---- */
        float s[8][4];
#pragma unroll
        for (int j = 0; j < 8; j++)
#pragma unroll
            for (int c = 0; c < 4; c++) s[j][c] = 0.f;

#pragma unroll
        for (int k16 = 0; k16 < 4; k16++) {
            uint32_t kb[8][2];
#pragma unroll
            for (int t = 0; t < 4; t++) {
                uint32_t d0, d1, d2, d3;
                LDSM4(d0, d1, d2, d3, kbase + lm_base[t] + k16 * 32);
                kb[2 * t][0] = d0;     kb[2 * t][1] = d1;
                kb[2 * t + 1][0] = d2; kb[2 * t + 1][1] = d3;
            }
#pragma unroll
            for (int j = 0; j < 8; j++)
                MMA_F16(s[j], qf[k16], kb[j][0], kb[j][1]);
        }

        /* ---- causal mask on diagonal tile ---- */
        const int r0 = mrow + ar, r1 = r0 + 8;
        if (kt == qt) {
#pragma unroll
            for (int j = 0; j < 8; j++) {
                const int c = j * 8 + 2 * ac;
                if (c     > r0) s[j][0] = -1e30f;
                if (c + 1 > r0) s[j][1] = -1e30f;
                if (c     > r1) s[j][2] = -1e30f;
                if (c + 1 > r1) s[j][3] = -1e30f;
            }
        }

        /* ---- online softmax: max + fused f16x2 exp2 ---- */
        float mx0 = -1e30f, mx1 = -1e30f;
#pragma unroll
        for (int j = 0; j < 8; j++) {
            mx0 = fmaxf(mx0, fmaxf(s[j][0], s[j][1]));
            mx1 = fmaxf(mx1, fmaxf(s[j][2], s[j][3]));
        }
        mx0 = fmaxf(mx0, __shfl_xor_sync(0xffffffffu, mx0, 1));
        mx0 = fmaxf(mx0, __shfl_xor_sync(0xffffffffu, mx0, 2));
        mx1 = fmaxf(mx1, __shfl_xor_sync(0xffffffffu, mx1, 1));
        mx1 = fmaxf(mx1, __shfl_xor_sync(0xffffffffu, mx1, 2));

        const float mn0 = fmaxf(m0, mx0), mn1 = fmaxf(m1, mx1);
        const float corr0 = exp2f(m0 - mn0), corr1 = exp2f(m1 - mn1);
        m0 = mn0; m1 = mn1;

        /* P fragments directly as packed fp16 pairs */
        uint32_t pe[8][2];
#pragma unroll
        for (int j = 0; j < 8; j++) {
            pe[j][0] = ex2_h2(s[j][0] - mn0, s[j][1] - mn0);
            pe[j][1] = ex2_h2(s[j][2] - mn1, s[j][3] - mn1);
        }
#pragma unroll
        for (int j = 0; j < 9; j++) {
            o[j][0] *= corr0; o[j][1] *= corr0;
            o[j][2] *= corr1; o[j][3] *= corr1;
        }

        /* ---- O += P V, and l += P·1 via ones-column MMA ---- */
#pragma unroll
        for (int k16 = 0; k16 < 4; k16++) {
            uint32_t pa[4];
            pa[0] = pe[2 * k16][0];
            pa[1] = pe[2 * k16][1];
            pa[2] = pe[2 * k16 + 1][0];
            pa[3] = pe[2 * k16 + 1][1];
            uint32_t vb[8][2];
#pragma unroll
            for (int t = 0; t < 4; t++) {
                uint32_t d0, d1, d2, d3;
                LDSM4(d0, d1, d2, d3, vbase + lm_base[t] + k16 * 32);
                vb[2 * t][0] = d0;     vb[2 * t][1] = d1;
                vb[2 * t + 1][0] = d2; vb[2 * t + 1][1] = d3;
            }
#pragma unroll
            for (int j = 0; j < 8; j++)
                MMA_F16(o[j], pa, vb[j][0], vb[j][1]);
            MMA_F16(o[8], pa, H2_ONES, H2_ONES);
        }
    }

    /* epilogue: l from ones column; normalize; write ctx fp16 [B*S, D] */
    const int b_ = bh >> 4, h = bh & (HH - 1);
    const float inv0 = 1.0f / o[8][0], inv1 = 1.0f / o[8][2];
    const int s0 = qt * 64 + mrow + ar, s1 = s0 + 8;
    __half* p0 = g_ctx + (size_t)(b_ * SS + s0) * DD + h * DHD;
    __half* p1 = g_ctx + (size_t)(b_ * SS + s1) * DD + h * DHD;
#pragma unroll
    for (int j = 0; j < 8; j++) {
        const int c = j * 8 + 2 * ac;
        *reinterpret_cast<__half2*>(&p0[c]) =
            __floats2half2_rn(o[j][0] * inv0, o[j][1] * inv0);
        *reinterpret_cast<__half2*>(&p1[c]) =
            __floats2half2_rn(o[j][2] * inv1, o[j][3] * inv1);
    }
}

/* ------------------------------------------------------------------ */
extern "C" void kernel_launch(void* const* d_in, const int* in_sizes, int n_in,
                              void* d_out, int out_size)
{
    (void)in_sizes; (void)n_in; (void)out_size;
    const float* x  = (const float*)d_in[0];
    const float* Wq = (const float*)d_in[1];
    const float* Wk = (const float*)d_in[2];
    const float* Wv = (const float*)d_in[3];
    const float* Wo = (const float*)d_in[4];
    const float* bo = (const float*)d_in[5];
    float* out = (float*)d_out;

    cudaFuncSetAttribute(qkv_h_kernel,  cudaFuncAttributeMaxDynamicSharedMemorySize, GM_SMEM);
    cudaFuncSetAttribute(out_h_kernel,  cudaFuncAttributeMaxDynamicSharedMemorySize, GM_SMEM);
    cudaFuncSetAttribute(attn_h_kernel, cudaFuncAttributeMaxDynamicSharedMemorySize, AT_SMEM);

    round_x_kernel<<<2048, 256>>>(x);
    wtrans_kernel<<<dim3(32, 32, 4), dim3(32, 8)>>>(Wq, Wk, Wv, Wo);

    dim3 gq(DD / 128, NROWS / 128, 3);
    qkv_h_kernel<<<gq, 128, GM_SMEM>>>();

    dim3 ga(SS / 64, BB * HH);
    attn_h_kernel<<<ga, 128, AT_SMEM>>>();

    dim3 go(DD / 128, NROWS / 128);
    out_h_kernel<<<go, 128, GM_SMEM>>>(bo, out);
}